// round 12
// baseline (speedup 1.0000x reference)
#include <cuda_runtime.h>
#include <cuda_bf16.h>
#include <math.h>
#include <stdint.h>

#define SEQ   1024
#define DIM   1024
#define NHEAD 16
#define HD    64
#define FFD   4096
#define DEPTH 24
#define OUTD  2560

// ---------------- weight hi/lo pools (uint32 = bf16x2 pair along K) --------
#define W_CONV   0u
#define W_QKV    786432u
#define W_PROJ   38535168u
#define W_FC1    51118080u
#define W_FC2    101449728u
#define W_MFC1   151781376u
#define W_DFC1   160169984u
#define W_MFC2   185335808u
#define W_DFC2   190578688u
#define W_TOTAL  206307328u

__device__ __align__(16) uint32_t g_wh[W_TOTAL];
__device__ __align__(16) uint32_t g_wl[W_TOTAL];

// ---------------- activation scratch ----------------------------------------
__device__ float g_x   [SEQ*DIM];
__device__ float g_cos [SEQ*HD];
__device__ float g_sin [SEQ*HD];
__device__ __align__(16) uint32_t g_hh [SEQ*DIM/2];
__device__ __align__(16) uint32_t g_hl [SEQ*DIM/2];
__device__ __align__(16) uint32_t g_ah [SEQ*DIM/2];
__device__ __align__(16) uint32_t g_al [SEQ*DIM/2];
__device__ __align__(16) uint32_t g_fh [SEQ*FFD/2];
__device__ __align__(16) uint32_t g_fl [SEQ*FFD/2];
__device__ __align__(16) uint32_t g_ph [SEQ*1536/2];
__device__ __align__(16) uint32_t g_pl [SEQ*1536/2];
__device__ __align__(16) uint32_t g_qh [NHEAD*SEQ*32];
__device__ __align__(16) uint32_t g_ql [NHEAD*SEQ*32];
__device__ __align__(16) uint32_t g_kh [NHEAD*SEQ*32];
__device__ __align__(16) uint32_t g_kl [NHEAD*SEQ*32];
__device__ __align__(16) uint32_t g_vth[NHEAD*HD*512];
__device__ __align__(16) uint32_t g_vtl[NHEAD*HD*512];
__device__ float g_ds  [3*SEQ*DIM];
__device__ __align__(16) uint32_t g_mh [4*524288];
__device__ __align__(16) uint32_t g_ml [4*524288];
__device__ __align__(16) uint32_t g_mfh[4*524288];
__device__ __align__(16) uint32_t g_mfl[4*524288];
__device__ float g_mb1[4*4096];
__device__ float g_mb2[4*2560];

__device__ __forceinline__ float gelu_exact(float x) {
    return 0.5f * x * (1.0f + erff(x * 0.70710678118654752f));
}

__device__ __forceinline__ void split2(float x, float y, uint32_t& hi, uint32_t& lo) {
    __nv_bfloat16 xh = __float2bfloat16(x);
    __nv_bfloat16 yh = __float2bfloat16(y);
    __nv_bfloat16 xl = __float2bfloat16(x - __bfloat162float(xh));
    __nv_bfloat16 yl = __float2bfloat16(y - __bfloat162float(yh));
    __nv_bfloat162 h2 = __halves2bfloat162(xh, yh);
    __nv_bfloat162 l2 = __halves2bfloat162(xl, yl);
    hi = *(uint32_t*)&h2;
    lo = *(uint32_t*)&l2;
}

#define MMA_BF16(d, a, b0, b1)                                                 \
    asm volatile("mma.sync.aligned.m16n8k16.row.col.f32.bf16.bf16.f32 "        \
                 "{%0,%1,%2,%3},{%4,%5,%6,%7},{%8,%9},{%0,%1,%2,%3};"          \
                 : "+f"(d[0]), "+f"(d[1]), "+f"(d[2]), "+f"(d[3])              \
                 : "r"(a[0]), "r"(a[1]), "r"(a[2]), "r"(a[3]), "r"(b0), "r"(b1))

#define LDSM_X4(r, addr)                                                       \
    asm volatile("ldmatrix.sync.aligned.m8n8.x4.shared.b16 {%0,%1,%2,%3},[%4];"\
                 : "=r"((r)[0]), "=r"((r)[1]), "=r"((r)[2]), "=r"((r)[3])      \
                 : "r"(addr))

#define CP_ASYNC16(dst, src)                                                   \
    asm volatile("cp.async.cg.shared.global [%0],[%1],16;" :: "r"(dst), "l"(src))
#define CP_COMMIT  asm volatile("cp.async.commit_group;")
#define CP_WAIT1   asm volatile("cp.async.wait_group 1;")

__device__ __forceinline__ uint32_t smem_u32(const void* p) {
    return (uint32_t)__cvta_generic_to_shared(p);
}

// ---------------- merged fp32 -> bf16 hi/lo conversion -----------------------
struct CvtTable {
    const float* src[9];
    uint32_t dstoff[9];
    uint32_t blkstart[10];
};

__global__ void convert_all(CvtTable tab, uint32_t* __restrict__ dh,
                            uint32_t* __restrict__ dl)
{
    int bid = blockIdx.x;
    int c = 0;
    while (bid >= (int)tab.blkstart[c + 1]) c++;
    size_t p = (size_t)(bid - tab.blkstart[c]) * 256 + threadIdx.x;
    const float* s = tab.src[c];
    float4 v = *(const float4*)(s + 4 * p);
    uint32_t h0, l0, h1, l1;
    split2(v.x, v.y, h0, l0);
    split2(v.z, v.w, h1, l1);
    size_t o = tab.dstoff[c] + 2 * p;
    *(uint2*)(dh + o) = make_uint2(h0, h1);
    *(uint2*)(dl + o) = make_uint2(l0, l1);
}

__global__ void convert_pairs(const float* __restrict__ src,
                              uint32_t* __restrict__ dh,
                              uint32_t* __restrict__ dl, int nwords)
{
    int i = blockIdx.x * blockDim.x + threadIdx.x;
    if (2 * i >= nwords) return;
    float4 v = *(const float4*)(src + 4 * (size_t)i);
    uint32_t h0, l0, h1, l1;
    split2(v.x, v.y, h0, l0);
    split2(v.z, v.w, h1, l1);
    *(uint2*)(dh + 2 * (size_t)i) = make_uint2(h0, h1);
    *(uint2*)(dl + 2 * (size_t)i) = make_uint2(l0, l1);
}

__global__ void bias_copy(const float* __restrict__ m1, const float* __restrict__ d1,
                          const float* __restrict__ m2, const float* __restrict__ d2,
                          float* __restrict__ o1, float* __restrict__ o2)
{
    int i = blockIdx.x * blockDim.x + threadIdx.x;
    if (i < 4 * 4096) {
        int b = i >> 12, k = i & 4095;
        o1[i] = (b == 0) ? m1[k] : d1[(b - 1) * 4096 + k];
    } else if (i < 4 * 4096 + 4 * 2560) {
        int j = i - 4 * 4096;
        int b = j / 2560, k = j % 2560;
        o2[j] = (b == 0) ? m2[k] : d2[(b - 1) * 2560 + k];
    }
}

// ---------------- templated GEMM: MT x 64 tile, 128 threads, 3-stage ---------
// MT=64: 4 warps stacked in M, warp covers all 64 N (needed by fused qkv epi).
// MT=32: 2x2 warps, warp covers 32 N. 45KB smem -> 4 CTAs/SM.
// flags: bit0 residual, bit1 gelu, bit2 write pairs, bit3 write fp32 C,
//        bit4 dup fp32 to C2, bit5 fused qkv rope/vt epilogue,
//        bit6 add pos-table (Cres = pos_table)
#define SW 20
#define NSTAGE 3
#define SMEM_OF(MT) (NSTAGE * (2 * (MT) * SW + 2 * 64 * SW) * 4)

template<int MT>
__global__ void __launch_bounds__(128, (MT == 64) ? 3 : 4) gemm_pre(
    const uint32_t* __restrict__ Ah, const uint32_t* __restrict__ Al,
    const uint32_t* __restrict__ Bh, const uint32_t* __restrict__ Bl,
    const float* __restrict__ bias, const float* __restrict__ Cres,
    float* __restrict__ C, uint32_t* __restrict__ Ch, uint32_t* __restrict__ Cl,
    float* __restrict__ C2, int M, int N, int K, int flags,
    int bsAw, int bsBw, int bsBias, int bsCE)
{
    constexpr int AW = MT * SW;              // words per A array
    constexpr int BW = 64 * SW;              // words per B array
    constexpr int STGW = 2 * AW + 2 * BW;
    constexpr int JJ = (MT == 64) ? 4 : 2;   // 16-col groups per warp
    constexpr int NLOAD = (2 * MT + 128) * 4 / 128;

    extern __shared__ uint32_t sm[];
    const int bz = blockIdx.z;
    Ah += (size_t)bz * bsAw;  Al += (size_t)bz * bsAw;
    Bh += (size_t)bz * bsBw;  Bl += (size_t)bz * bsBw;
    bias += (size_t)bz * bsBias;
    C  += (size_t)bz * bsCE;
    C2 += (size_t)bz * bsCE;
    Ch += (size_t)bz * (bsCE >> 1);
    Cl += (size_t)bz * (bsCE >> 1);

    const int bm = blockIdx.y * MT, bn = blockIdx.x * 64;
    const int tid = threadIdx.x;
    const int wid = tid >> 5, lane = tid & 31;
    const int wm = (MT == 64) ? wid : (wid >> 1);
    const int nbase = (MT == 64) ? 0 : ((wid & 1) * 32);
    const int Kw = K >> 1;
    const int NT = Kw >> 4;

    float acc[2 * JJ][4];
#pragma unroll
    for (int j = 0; j < 2 * JJ; j++)
#pragma unroll
        for (int c = 0; c < 4; c++) acc[j][c] = 0.f;

    const uint32_t smbase = smem_u32(sm);

    const int aRow  = lane & 15;
    const int aColw = (lane >> 4) << 2;
    const int bRow  = (lane & 7) + ((lane & 16) ? 8 : 0);
    const int bColw = (lane & 8) ? 4 : 0;

#define LOAD_SLAB(stagebase_, kwo_) do {                                       \
    _Pragma("unroll")                                                          \
    for (int it = 0; it < NLOAD; it++) {                                       \
        int idx = tid + it * 128;                                              \
        uint32_t smoff; const uint32_t* gp;                                    \
        if (idx < 2 * MT * 4) {                                                \
            int which = idx >= MT * 4;                                         \
            int r = (idx >> 2) & (MT - 1), c = idx & 3;                        \
            smoff = (uint32_t)(which * AW + r * SW + c * 4);                   \
            gp = (which ? Al : Ah) + (size_t)(bm + r) * Kw + (kwo_) + c * 4;   \
        } else {                                                               \
            int rem = idx - 2 * MT * 4;                                        \
            int which = rem >> 8, r = (rem >> 2) & 63, c = rem & 3;            \
            smoff = (uint32_t)(2 * AW + which * BW + r * SW + c * 4);          \
            gp = (which ? Bl : Bh) + (size_t)(bn + r) * Kw + (kwo_) + c * 4;   \
        }                                                                      \
        CP_ASYNC16((stagebase_) + smoff * 4, gp);                              \
    }                                                                          \
} while (0)

    LOAD_SLAB(smbase, 0);
    CP_COMMIT;
    if (NT > 1) LOAD_SLAB(smbase + STGW * 4, 16);
    CP_COMMIT;

    for (int kt = 0; kt < NT; kt++) {
        const int s = kt % NSTAGE;
        CP_WAIT1;
        __syncthreads();

        if (kt + 2 < NT) {
            const uint32_t stb = smbase + ((kt + 2) % NSTAGE) * STGW * 4;
            LOAD_SLAB(stb, (kt + 2) * 16);
        }
        CP_COMMIT;

        const uint32_t base   = smbase + (uint32_t)(s * STGW) * 4;
        const uint32_t baseAh = base;
        const uint32_t baseAl = base + (uint32_t)AW * 4;
        const uint32_t baseBh = base + (uint32_t)(2 * AW) * 4;
        const uint32_t baseBl = base + (uint32_t)(2 * AW + BW) * 4;

#pragma unroll
        for (int ks = 0; ks < 2; ks++) {
            uint32_t ah[4], al[4];
            {
                uint32_t off = (uint32_t)((wm * 16 + aRow) * SW + ks * 8 + aColw) * 4;
                LDSM_X4(ah, baseAh + off);
                LDSM_X4(al, baseAl + off);
            }
            uint32_t bh[JJ][4], bl[JJ][4];
#pragma unroll
            for (int jj = 0; jj < JJ; jj++) {
                uint32_t off = (uint32_t)((nbase + jj * 16 + bRow) * SW
                                          + ks * 8 + bColw) * 4;
                LDSM_X4(bh[jj], baseBh + off);
                LDSM_X4(bl[jj], baseBl + off);
            }
#pragma unroll
            for (int jj = 0; jj < JJ; jj++)
#pragma unroll
                for (int jp = 0; jp < 2; jp++)
                    MMA_BF16(acc[jj*2+jp], ah, bh[jj][jp*2], bh[jj][jp*2+1]);
#pragma unroll
            for (int jj = 0; jj < JJ; jj++)
#pragma unroll
                for (int jp = 0; jp < 2; jp++)
                    MMA_BF16(acc[jj*2+jp], ah, bl[jj][jp*2], bl[jj][jp*2+1]);
#pragma unroll
            for (int jj = 0; jj < JJ; jj++)
#pragma unroll
                for (int jp = 0; jp < 2; jp++)
                    MMA_BF16(acc[jj*2+jp], al, bh[jj][jp*2], bh[jj][jp*2+1]);
        }
    }

    if (MT == 64 && (flags & 32)) {
        // ---- fused qkv epilogue: rope q/k + v transpose, bias only ----
        const int r0 = bm + wm * 16 + (lane >> 2);
        const int colbase = bn;
        const int region = colbase >> 10;
        const int h = (colbase & 1023) >> 6;
#pragma unroll
        for (int half = 0; half < 2; half++) {
            const int t = r0 + half * 8;
            float vals[8][2];
#pragma unroll
            for (int j = 0; j < 2 * JJ; j++) {
                int col = colbase + j * 8 + (lane & 3) * 2;
                vals[j][0] = acc[j][half * 2 + 0] + bias[col];
                vals[j][1] = acc[j][half * 2 + 1] + bias[col + 1];
            }
            if (region < 2) {
                uint32_t* Oh = region ? g_kh : g_qh;
                uint32_t* Ol = region ? g_kl : g_ql;
                const float qs = region ? 1.0f : 0.125f;
                const size_t ob = ((size_t)(h << 10) + t) * 32;
#pragma unroll
                for (int j = 0; j < 4; j++) {
                    int d = j * 8 + (lane & 3) * 2;
                    float c0 = g_cos[t*64 + d],      s0 = g_sin[t*64 + d];
                    float c1 = g_cos[t*64 + d + 1],  s1 = g_sin[t*64 + d + 1];
                    float c2 = g_cos[t*64 + d + 32], s2 = g_sin[t*64 + d + 32];
                    float c3 = g_cos[t*64 + d + 33], s3 = g_sin[t*64 + d + 33];
                    float x1a = vals[j][0],     x1b = vals[j][1];
                    float x2a = vals[j + 4][0], x2b = vals[j + 4][1];
                    uint32_t hh, ll;
                    split2((x1a*c0 - x2a*s0) * qs, (x1b*c1 - x2b*s1) * qs, hh, ll);
                    Oh[ob + (d >> 1)] = hh;  Ol[ob + (d >> 1)] = ll;
                    split2((x2a*c2 + x1a*s2) * qs, (x2b*c3 + x1b*s3) * qs, hh, ll);
                    Oh[ob + (d >> 1) + 16] = hh;  Ol[ob + (d >> 1) + 16] = ll;
                }
            } else {
                const int tp = t >> 1;
#pragma unroll
                for (int j = 0; j < 2 * JJ; j++) {
                    float p0 = __shfl_down_sync(0xFFFFFFFFu, vals[j][0], 4);
                    float p1 = __shfl_down_sync(0xFFFFFFFFu, vals[j][1], 4);
                    if ((lane & 4) == 0) {
                        int d = j * 8 + (lane & 3) * 2;
                        uint32_t hh, ll;
                        split2(vals[j][0], p0, hh, ll);
                        g_vth[(size_t)(h * 64 + d) * 512 + tp] = hh;
                        g_vtl[(size_t)(h * 64 + d) * 512 + tp] = ll;
                        split2(vals[j][1], p1, hh, ll);
                        g_vth[(size_t)(h * 64 + d + 1) * 512 + tp] = hh;
                        g_vtl[(size_t)(h * 64 + d + 1) * 512 + tp] = ll;
                    }
                }
            }
        }
        return;
    }

    // standard epilogue
    {
        const int r0 = bm + wm * 16 + (lane >> 2);
#pragma unroll
        for (int j = 0; j < 2 * JJ; j++) {
            int col = bn + nbase + j * 8 + (lane & 3) * 2;
            float b0 = bias[col], b1 = bias[col + 1];
#pragma unroll
            for (int half = 0; half < 2; half++) {
                int row = r0 + half * 8;
                float v0 = acc[j][half * 2 + 0] + b0;
                float v1 = acc[j][half * 2 + 1] + b1;
                if (flags & 2) { v0 = gelu_exact(v0); v1 = gelu_exact(v1); }
                if (flags & 1) {
                    const float* R = Cres + (size_t)row * N + col;
                    v0 += R[0]; v1 += R[1];
                }
                if (flags & 64) {
                    int bhh = row >> 6, rr = row & 63;
                    int pid = ((bhh * 2 + ((rr >> 1) & 1)) * 48)
                              + ((rr >> 2) * 2 + (rr & 1));
                    const float* P = Cres + (size_t)pid * DIM + col;
                    v0 += P[0]; v1 += P[1];
                }
                if (flags & 8)
                    *(float2*)(C + (size_t)row * N + col) = make_float2(v0, v1);
                if (flags & 16)
                    *(float2*)(C2 + (size_t)row * N + col) = make_float2(v0, v1);
                if (flags & 4) {
                    uint32_t hh, ll;
                    split2(v0, v1, hh, ll);
                    Ch[(size_t)row * (N >> 1) + (col >> 1)] = hh;
                    Cl[(size_t)row * (N >> 1) + (col >> 1)] = ll;
                }
            }
        }
    }
#undef LOAD_SLAB
}

// ---------------- LayerNorm -> hi/lo pairs ----------------------------------
__global__ void __launch_bounds__(256) ln_pairs(
    const float* __restrict__ x, const float* __restrict__ s,
    const float* __restrict__ b, uint32_t* __restrict__ yh,
    uint32_t* __restrict__ yl, int W)
{
    __shared__ float red[9];
    const int row = blockIdx.x;
    const int tid = threadIdx.x;
    const float* xr = x + (size_t)row * W;

    float sum = 0.f;
    for (int i = tid; i < W; i += 256) sum += xr[i];
#pragma unroll
    for (int o = 16; o > 0; o >>= 1) sum += __shfl_xor_sync(~0u, sum, o);
    if ((tid & 31) == 0) red[tid >> 5] = sum;
    __syncthreads();
    if (tid == 0) {
        float t = 0.f;
        for (int w = 0; w < 8; w++) t += red[w];
        red[8] = t;
    }
    __syncthreads();
    const float mu = red[8] / (float)W;

    float var = 0.f;
    for (int i = tid; i < W; i += 256) { float d = xr[i] - mu; var += d * d; }
    __syncthreads();
#pragma unroll
    for (int o = 16; o > 0; o >>= 1) var += __shfl_xor_sync(~0u, var, o);
    if ((tid & 31) == 0) red[tid >> 5] = var;
    __syncthreads();
    if (tid == 0) {
        float t = 0.f;
        for (int w = 0; w < 8; w++) t += red[w];
        red[8] = t;
    }
    __syncthreads();
    const float inv = rsqrtf(red[8] / (float)W + 1e-6f);

    const int Ww = W >> 1;
    for (int i = tid; i < Ww; i += 256) {
        float v0 = (xr[2*i]   - mu) * inv * s[2*i]   + b[2*i];
        float v1 = (xr[2*i+1] - mu) * inv * s[2*i+1] + b[2*i+1];
        uint32_t hh, ll;
        split2(v0, v1, hh, ll);
        yh[(size_t)row * Ww + i] = hh;
        yl[(size_t)row * Ww + i] = ll;
    }
}

// ---------------- RoPE table init -------------------------------------------
__global__ void init_rope(float* __restrict__ cosT, float* __restrict__ sinT)
{
    int idx = blockIdx.x * blockDim.x + threadIdx.x;
    if (idx >= SEQ * HD) return;
    int t = idx >> 6, d = idx & 63;
    int bh = t >> 6, r = t & 63, bw = r >> 2, ih = (r >> 1) & 1, iw = r & 1;
    float hp = (float)(bh * 2 + ih);
    float wp = (float)(bw * 2 + iw);
    int base = d & 31;
    float pos, inv;
    if (base < 16) { pos = hp; inv = powf(10000.f, -(float)base / 16.f); }
    else           { pos = wp; inv = powf(10000.f, -(float)(base - 16) / 16.f); }
    float ang = pos * inv;
    cosT[idx] = cosf(ang);
    sinT[idx] = sinf(ang);
}

// ---------------- tensor-core flash attention -------------------------------
__global__ void __launch_bounds__(256) attn_mma(
    const uint32_t* __restrict__ qh, const uint32_t* __restrict__ ql,
    const uint32_t* __restrict__ kh, const uint32_t* __restrict__ kl,
    const uint32_t* __restrict__ vth, const uint32_t* __restrict__ vtl,
    uint32_t* __restrict__ oh, uint32_t* __restrict__ ol)
{
    __shared__ uint32_t sKh[64*33], sKl[64*33], sVh[64*33], sVl[64*33];
    const int h = blockIdx.y, qt = blockIdx.x;
    const int tid = threadIdx.x, w = tid >> 5, lane = tid & 31;
    const int gq = lane >> 2, l4 = lane & 3;
    const int qrow = qt * 128 + w * 16 + gq;

    uint32_t qfh[4][4], qfl[4][4];
    {
        const uint32_t* bh = qh + ((size_t)(h << 10) + qrow) * 32;
        const uint32_t* bl = ql + ((size_t)(h << 10) + qrow) * 32;
#pragma unroll
        for (int ks = 0; ks < 4; ks++) {
            int kp = ks * 8 + l4;
            qfh[ks][0] = bh[kp];        qfh[ks][1] = bh[8*32 + kp];
            qfh[ks][2] = bh[kp + 4];    qfh[ks][3] = bh[8*32 + kp + 4];
            qfl[ks][0] = bl[kp];        qfl[ks][1] = bl[8*32 + kp];
            qfl[ks][2] = bl[kp + 4];    qfl[ks][3] = bl[8*32 + kp + 4];
        }
    }

    float m0 = -1e30f, m1 = -1e30f, L0 = 0.f, L1 = 0.f;
    float O[8][4];
#pragma unroll
    for (int j = 0; j < 8; j++)
#pragma unroll
        for (int c = 0; c < 4; c++) O[j][c] = 0.f;

    for (int kt = 0; kt < SEQ; kt += 64) {
        __syncthreads();
        {
            const uint32_t* Kh = kh + ((size_t)(h << 10) + kt) * 32;
            const uint32_t* Kl = kl + ((size_t)(h << 10) + kt) * 32;
            const uint32_t* Vh = vth + (size_t)(h * 64) * 512 + (kt >> 1);
            const uint32_t* Vl = vtl + (size_t)(h * 64) * 512 + (kt >> 1);
            for (int u = tid; u < 64 * 32; u += 256) {
                int r = u >> 5, c = u & 31;
                sKh[r * 33 + c] = Kh[r * 32 + c];
                sKl[r * 33 + c] = Kl[r * 32 + c];
                sVh[r * 33 + c] = Vh[(size_t)r * 512 + c];
                sVl[r * 33 + c] = Vl[(size_t)r * 512 + c];
            }
        }
        __syncthreads();

        float sacc[8][4];
#pragma unroll
        for (int j = 0; j < 8; j++) {
            sacc[j][0] = sacc[j][1] = sacc[j][2] = sacc[j][3] = 0.f;
            int n = j * 8 + gq;
#pragma unroll
            for (int ks = 0; ks < 4; ks++) {
                int kp = ks * 8 + l4;
                uint32_t bh0 = sKh[n * 33 + kp], bh1 = sKh[n * 33 + kp + 4];
                uint32_t bl0 = sKl[n * 33 + kp], bl1 = sKl[n * 33 + kp + 4];
                MMA_BF16(sacc[j], qfh[ks], bh0, bh1);
                MMA_BF16(sacc[j], qfh[ks], bl0, bl1);
                MMA_BF16(sacc[j], qfl[ks], bh0, bh1);
            }
        }

        float mt0 = -1e30f, mt1 = -1e30f;
#pragma unroll
        for (int j = 0; j < 8; j++) {
            mt0 = fmaxf(mt0, fmaxf(sacc[j][0], sacc[j][1]));
            mt1 = fmaxf(mt1, fmaxf(sacc[j][2], sacc[j][3]));
        }
        mt0 = fmaxf(mt0, __shfl_xor_sync(~0u, mt0, 1));
        mt0 = fmaxf(mt0, __shfl_xor_sync(~0u, mt0, 2));
        mt1 = fmaxf(mt1, __shfl_xor_sync(~0u, mt1, 1));
        mt1 = fmaxf(mt1, __shfl_xor_sync(~0u, mt1, 2));
        float mn0 = fmaxf(m0, mt0), mn1 = fmaxf(m1, mt1);
        float sc0 = __expf(m0 - mn0), sc1 = __expf(m1 - mn1);
        float ls0 = 0.f, ls1 = 0.f;
#pragma unroll
        for (int j = 0; j < 8; j++) {
            sacc[j][0] = __expf(sacc[j][0] - mn0);
            sacc[j][1] = __expf(sacc[j][1] - mn0);
            sacc[j][2] = __expf(sacc[j][2] - mn1);
            sacc[j][3] = __expf(sacc[j][3] - mn1);
            ls0 += sacc[j][0] + sacc[j][1];
            ls1 += sacc[j][2] + sacc[j][3];
        }
        ls0 += __shfl_xor_sync(~0u, ls0, 1);
        ls0 += __shfl_xor_sync(~0u, ls0, 2);
        ls1 += __shfl_xor_sync(~0u, ls1, 1);
        ls1 += __shfl_xor_sync(~0u, ls1, 2);
        L0 = L0 * sc0 + ls0;
        L1 = L1 * sc1 + ls1;
        m0 = mn0; m1 = mn1;
#pragma unroll
        for (int j = 0; j < 8; j++) {
            O[j][0] *= sc0; O[j][1] *= sc0;
            O[j][2] *= sc1; O[j][3] *= sc1;
        }

        uint32_t pfh[4][4], pfl[4][4];
#pragma unroll
        for (int ks2 = 0; ks2 < 4; ks2++) {
            int j0 = 2 * ks2, j1 = j0 + 1;
            split2(sacc[j0][0], sacc[j0][1], pfh[ks2][0], pfl[ks2][0]);
            split2(sacc[j0][2], sacc[j0][3], pfh[ks2][1], pfl[ks2][1]);
            split2(sacc[j1][0], sacc[j1][1], pfh[ks2][2], pfl[ks2][2]);
            split2(sacc[j1][2], sacc[j1][3], pfh[ks2][3], pfl[ks2][3]);
        }

#pragma unroll
        for (int jd = 0; jd < 8; jd++) {
            int n = jd * 8 + gq;
#pragma unroll
            for (int ks2 = 0; ks2 < 4; ks2++) {
                int kp = ks2 * 8 + l4;
                uint32_t bh0 = sVh[n * 33 + kp], bh1 = sVh[n * 33 + kp + 4];
                uint32_t bl0 = sVl[n * 33 + kp], bl1 = sVl[n * 33 + kp + 4];
                MMA_BF16(O[jd], pfh[ks2], bh0, bh1);
                MMA_BF16(O[jd], pfh[ks2], bl0, bl1);
                MMA_BF16(O[jd], pfl[ks2], bh0, bh1);
            }
        }
    }

    float inv0 = 1.0f / L0, inv1 = 1.0f / L1;
#pragma unroll
    for (int jd = 0; jd < 8; jd++) {
        int word = h * 32 + jd * 4 + l4;
        uint32_t hh, ll;
        split2(O[jd][0] * inv0, O[jd][1] * inv0, hh, ll);
        oh[(size_t)qrow * 512 + word] = hh;
        ol[(size_t)qrow * 512 + word] = ll;
        split2(O[jd][2] * inv1, O[jd][3] * inv1, hh, ll);
        oh[(size_t)(qrow + 8) * 512 + word] = hh;
        ol[(size_t)(qrow + 8) * 512 + word] = ll;
    }
}

// ---------------- launch -----------------------------------------------------
extern "C" void kernel_launch(void* const* d_in, const int* in_sizes, int n_in,
                              void* d_out, int out_size)
{
    (void)in_sizes; (void)n_in; (void)out_size;
    const float* pixel     = (const float*)d_in[0];
    const float* conv_w    = (const float*)d_in[1];
    const float* conv_b    = (const float*)d_in[2];
    const float* pos_table = (const float*)d_in[3];
    const float* ln1_s     = (const float*)d_in[4];
    const float* ln1_b     = (const float*)d_in[5];
    const float* ln2_s     = (const float*)d_in[6];
    const float* ln2_b     = (const float*)d_in[7];
    const float* qkv_w     = (const float*)d_in[8];
    const float* qkv_b     = (const float*)d_in[9];
    const float* proj_w    = (const float*)d_in[10];
    const float* proj_b    = (const float*)d_in[11];
    const float* fc1_w     = (const float*)d_in[12];
    const float* fc1_b     = (const float*)d_in[13];
    const float* fc2_w     = (const float*)d_in[14];
    const float* fc2_b     = (const float*)d_in[15];
    const float* mrg_ln_s  = (const float*)d_in[16];
    const float* mrg_ln_b  = (const float*)d_in[17];
    const float* mrg_fc1_w = (const float*)d_in[18];
    const float* mrg_fc1_b = (const float*)d_in[19];
    const float* mrg_fc2_w = (const float*)d_in[20];
    const float* mrg_fc2_b = (const float*)d_in[21];
    const float* ds_ln_s   = (const float*)d_in[22];
    const float* ds_ln_b   = (const float*)d_in[23];
    const float* ds_fc1_w  = (const float*)d_in[24];
    const float* ds_fc1_b  = (const float*)d_in[25];
    const float* ds_fc2_w  = (const float*)d_in[26];
    const float* ds_fc2_b  = (const float*)d_in[27];
    float* out = (float*)d_out;

    uint32_t *wh, *wl, *hh, *hl, *ah, *al, *fh, *fl, *ph, *pl;
    uint32_t *qhp, *qlp, *khp, *klp, *vth, *vtl;
    uint32_t *mh, *ml, *mfh, *mfl;
    float *x, *ds, *cosT, *sinT, *mb1, *mb2;
    cudaGetSymbolAddress((void**)&wh,  g_wh);
    cudaGetSymbolAddress((void**)&wl,  g_wl);
    cudaGetSymbolAddress((void**)&hh,  g_hh);
    cudaGetSymbolAddress((void**)&hl,  g_hl);
    cudaGetSymbolAddress((void**)&ah,  g_ah);
    cudaGetSymbolAddress((void**)&al,  g_al);
    cudaGetSymbolAddress((void**)&fh,  g_fh);
    cudaGetSymbolAddress((void**)&fl,  g_fl);
    cudaGetSymbolAddress((void**)&ph,  g_ph);
    cudaGetSymbolAddress((void**)&pl,  g_pl);
    cudaGetSymbolAddress((void**)&qhp, g_qh);
    cudaGetSymbolAddress((void**)&qlp, g_ql);
    cudaGetSymbolAddress((void**)&khp, g_kh);
    cudaGetSymbolAddress((void**)&klp, g_kl);
    cudaGetSymbolAddress((void**)&vth, g_vth);
    cudaGetSymbolAddress((void**)&vtl, g_vtl);
    cudaGetSymbolAddress((void**)&mh,  g_mh);
    cudaGetSymbolAddress((void**)&ml,  g_ml);
    cudaGetSymbolAddress((void**)&mfh, g_mfh);
    cudaGetSymbolAddress((void**)&mfl, g_mfl);
    cudaGetSymbolAddress((void**)&x,    g_x);
    cudaGetSymbolAddress((void**)&ds,   g_ds);
    cudaGetSymbolAddress((void**)&cosT, g_cos);
    cudaGetSymbolAddress((void**)&sinT, g_sin);
    cudaGetSymbolAddress((void**)&mb1,  g_mb1);
    cudaGetSymbolAddress((void**)&mb2,  g_mb2);

    cudaFuncSetAttribute(gemm_pre<64>,
                         cudaFuncAttributeMaxDynamicSharedMemorySize, SMEM_OF(64));
    cudaFuncSetAttribute(gemm_pre<32>,
                         cudaFuncAttributeMaxDynamicSharedMemorySize, SMEM_OF(32));

    // ---- single merged weight-conversion launch ----
    CvtTable tab;
    const float* srcs[9] = { conv_w, qkv_w, proj_w, fc1_w, fc2_w,
                             mrg_fc1_w, ds_fc1_w, mrg_fc2_w, ds_fc2_w };
    const uint32_t offs[9] = { W_CONV, W_QKV, W_PROJ, W_FC1, W_FC2,
                               W_MFC1, W_DFC1, W_MFC2, W_DFC2 };
    const uint32_t nws[9] = { W_QKV - W_CONV, W_PROJ - W_QKV, W_FC1 - W_PROJ,
                              W_FC2 - W_FC1, W_MFC1 - W_FC2, W_DFC1 - W_MFC1,
                              W_MFC2 - W_DFC1, W_DFC2 - W_MFC2, W_TOTAL - W_DFC2 };
    uint32_t blk = 0;
    for (int c = 0; c < 9; c++) {
        tab.src[c] = srcs[c];
        tab.dstoff[c] = offs[c];
        tab.blkstart[c] = blk;
        blk += nws[c] >> 9;
    }
    tab.blkstart[9] = blk;
    convert_all<<<blk, 256>>>(tab, wh, wl);
    convert_pairs<<<(SEQ * 768 / 2 + 255) / 256, 256>>>(pixel, ph, pl, SEQ * 768);
    init_rope<<<(SEQ * HD + 255) / 256, 256>>>(cosT, sinT);

    // patch embed + fused pos add
    gemm_pre<32><<<dim3(DIM / 64, SEQ / 32), 128, SMEM_OF(32)>>>(
        ph, pl, wh + W_CONV, wl + W_CONV, conv_b, pos_table, x, nullptr, nullptr,
        nullptr, SEQ, DIM, 1536, 8 | 64, 0, 0, 0, 0);

    for (int i = 0; i < DEPTH; i++) {
        ln_pairs<<<SEQ, 256>>>(x, ln1_s + i * DIM, ln1_b + i * DIM, hh, hl, DIM);
        gemm_pre<64><<<dim3(3 * DIM / 64, SEQ / 64), 128, SMEM_OF(64)>>>(
            hh, hl, wh + W_QKV + (size_t)i * (3 * DIM * DIM / 2),
            wl + W_QKV + (size_t)i * (3 * DIM * DIM / 2),
            qkv_b + (size_t)i * 3 * DIM, nullptr, nullptr, nullptr, nullptr,
            nullptr, SEQ, 3 * DIM, DIM, 32, 0, 0, 0, 0);
        attn_mma<<<dim3(SEQ / 128, NHEAD), 256>>>(qhp, qlp, khp, klp, vth, vtl, ah, al);
        gemm_pre<32><<<dim3(DIM / 64, SEQ / 32), 128, SMEM_OF(32)>>>(
            ah, al, wh + W_PROJ + (size_t)i * (DIM * DIM / 2),
            wl + W_PROJ + (size_t)i * (DIM * DIM / 2),
            proj_b + (size_t)i * DIM, x, x, nullptr, nullptr,
            nullptr, SEQ, DIM, DIM, 1 | 8, 0, 0, 0, 0);
        ln_pairs<<<SEQ, 256>>>(x, ln2_s + i * DIM, ln2_b + i * DIM, hh, hl, DIM);
        gemm_pre<32><<<dim3(FFD / 64, SEQ / 32), 128, SMEM_OF(32)>>>(
            hh, hl, wh + W_FC1 + (size_t)i * (FFD * DIM / 2),
            wl + W_FC1 + (size_t)i * (FFD * DIM / 2),
            fc1_b + (size_t)i * FFD, nullptr, nullptr, fh, fl,
            nullptr, SEQ, FFD, DIM, 2 | 4, 0, 0, 0, 0);

        int fc2_flags = 1 | 8;
        float* dup = nullptr;
        if (i == 5)  { fc2_flags |= 16; dup = ds; }
        if (i == 11) { fc2_flags |= 16; dup = ds + SEQ * DIM; }
        if (i == 17) { fc2_flags |= 16; dup = ds + 2 * SEQ * DIM; }
        if (i == 23) { fc2_flags |= 16; dup = out; }
        gemm_pre<32><<<dim3(DIM / 64, SEQ / 32), 128, SMEM_OF(32)>>>(
            fh, fl, wh + W_FC2 + (size_t)i * (DIM * FFD / 2),
            wl + W_FC2 + (size_t)i * (DIM * FFD / 2),
            fc2_b + (size_t)i * DIM, x, x, nullptr, nullptr,
            dup, SEQ, DIM, FFD, fc2_flags, 0, 0, 0, 0);

        if (i == 0)
            bias_copy<<<104, 256>>>(mrg_fc1_b, ds_fc1_b, mrg_fc2_b, ds_fc2_b, mb1, mb2);
    }

    // ---- batched mergers: batch 0 = pooled, 1..3 = deepstack ----
    ln_pairs<<<SEQ, 256>>>(x, mrg_ln_s, mrg_ln_b, mh, ml, DIM);
    for (int j = 0; j < 3; j++)
        ln_pairs<<<256, 256>>>(ds + (size_t)j * SEQ * DIM,
                               ds_ln_s + j * 4096, ds_ln_b + j * 4096,
                               mh + (size_t)(j + 1) * 524288,
                               ml + (size_t)(j + 1) * 524288, 4096);
    gemm_pre<32><<<dim3(4096 / 64, 256 / 32, 4), 128, SMEM_OF(32)>>>(
        mh, ml, wh + W_MFC1, wl + W_MFC1, mb1, nullptr, nullptr, mfh, mfl,
        nullptr, 256, 4096, 4096, 2 | 4,
        524288, 8388608, 4096, 1048576);
    gemm_pre<32><<<dim3(OUTD / 64, 256 / 32, 4), 128, SMEM_OF(32)>>>(
        mfh, mfl, wh + W_MFC2, wl + W_MFC2, mb2, nullptr, out + SEQ * DIM,
        nullptr, nullptr, nullptr, 256, OUTD, 4096, 8,
        524288, 5242880, 2560, 655360);
}

// round 13
// speedup vs baseline: 1.0622x; 1.0622x over previous
#include <cuda_runtime.h>
#include <cuda_bf16.h>
#include <math.h>
#include <stdint.h>

#define SEQ   1024
#define DIM   1024
#define NHEAD 16
#define HD    64
#define FFD   4096
#define DEPTH 24
#define OUTD  2560

// ---------------- weight hi/lo pools (uint32 = bf16x2 pair along K) --------
#define W_CONV   0u
#define W_QKV    786432u
#define W_PROJ   38535168u
#define W_FC1    51118080u
#define W_FC2    101449728u
#define W_MFC1   151781376u
#define W_DFC1   160169984u
#define W_MFC2   185335808u
#define W_DFC2   190578688u
#define W_TOTAL  206307328u

__device__ __align__(16) uint32_t g_wh[W_TOTAL];
__device__ __align__(16) uint32_t g_wl[W_TOTAL];

// ---------------- activation scratch ----------------------------------------
__device__ float g_x   [SEQ*DIM];
__device__ float g_cos [SEQ*HD];
__device__ float g_sin [SEQ*HD];
__device__ __align__(16) uint32_t g_hh [SEQ*DIM/2];
__device__ __align__(16) uint32_t g_hl [SEQ*DIM/2];
__device__ __align__(16) uint32_t g_ah [SEQ*DIM/2];
__device__ __align__(16) uint32_t g_al [SEQ*DIM/2];
__device__ __align__(16) uint32_t g_fh [SEQ*FFD/2];
__device__ __align__(16) uint32_t g_fl [SEQ*FFD/2];
__device__ __align__(16) uint32_t g_ph [SEQ*1536/2];
__device__ __align__(16) uint32_t g_pl [SEQ*1536/2];
__device__ __align__(16) uint32_t g_qh [NHEAD*SEQ*32];
__device__ __align__(16) uint32_t g_ql [NHEAD*SEQ*32];
__device__ __align__(16) uint32_t g_kh [NHEAD*SEQ*32];
__device__ __align__(16) uint32_t g_kl [NHEAD*SEQ*32];
__device__ __align__(16) uint32_t g_vth[NHEAD*HD*512];
__device__ __align__(16) uint32_t g_vtl[NHEAD*HD*512];
__device__ float g_ds  [3*SEQ*DIM];
__device__ __align__(16) uint32_t g_mh [4*524288];
__device__ __align__(16) uint32_t g_ml [4*524288];
__device__ __align__(16) uint32_t g_mfh[4*524288];
__device__ __align__(16) uint32_t g_mfl[4*524288];
__device__ float g_mb1[4*4096];
__device__ float g_mb2[4*2560];

__device__ __forceinline__ float gelu_exact(float x) {
    return 0.5f * x * (1.0f + erff(x * 0.70710678118654752f));
}

__device__ __forceinline__ void split2(float x, float y, uint32_t& hi, uint32_t& lo) {
    __nv_bfloat16 xh = __float2bfloat16(x);
    __nv_bfloat16 yh = __float2bfloat16(y);
    __nv_bfloat16 xl = __float2bfloat16(x - __bfloat162float(xh));
    __nv_bfloat16 yl = __float2bfloat16(y - __bfloat162float(yh));
    __nv_bfloat162 h2 = __halves2bfloat162(xh, yh);
    __nv_bfloat162 l2 = __halves2bfloat162(xl, yl);
    hi = *(uint32_t*)&h2;
    lo = *(uint32_t*)&l2;
}

#define MMA_BF16(d, a, b0, b1)                                                 \
    asm volatile("mma.sync.aligned.m16n8k16.row.col.f32.bf16.bf16.f32 "        \
                 "{%0,%1,%2,%3},{%4,%5,%6,%7},{%8,%9},{%0,%1,%2,%3};"          \
                 : "+f"(d[0]), "+f"(d[1]), "+f"(d[2]), "+f"(d[3])              \
                 : "r"(a[0]), "r"(a[1]), "r"(a[2]), "r"(a[3]), "r"(b0), "r"(b1))

#define LDSM_X4(r, addr)                                                       \
    asm volatile("ldmatrix.sync.aligned.m8n8.x4.shared.b16 {%0,%1,%2,%3},[%4];"\
                 : "=r"((r)[0]), "=r"((r)[1]), "=r"((r)[2]), "=r"((r)[3])      \
                 : "r"(addr))

#define CP_ASYNC16(dst, src)                                                   \
    asm volatile("cp.async.cg.shared.global [%0],[%1],16;" :: "r"(dst), "l"(src))
#define CP_COMMIT  asm volatile("cp.async.commit_group;")
#define CP_WAIT1   asm volatile("cp.async.wait_group 1;")

__device__ __forceinline__ uint32_t smem_u32(const void* p) {
    return (uint32_t)__cvta_generic_to_shared(p);
}

// ---------------- merged fp32 -> bf16 hi/lo conversion -----------------------
struct CvtTable {
    const float* src[9];
    uint32_t dstoff[9];
    uint32_t blkstart[10];
};

__global__ void convert_all(CvtTable tab, uint32_t* __restrict__ dh,
                            uint32_t* __restrict__ dl)
{
    int bid = blockIdx.x;
    int c = 0;
    while (bid >= (int)tab.blkstart[c + 1]) c++;
    size_t p = (size_t)(bid - tab.blkstart[c]) * 256 + threadIdx.x;
    const float* s = tab.src[c];
    float4 v = *(const float4*)(s + 4 * p);
    uint32_t h0, l0, h1, l1;
    split2(v.x, v.y, h0, l0);
    split2(v.z, v.w, h1, l1);
    size_t o = tab.dstoff[c] + 2 * p;
    *(uint2*)(dh + o) = make_uint2(h0, h1);
    *(uint2*)(dl + o) = make_uint2(l0, l1);
}

__global__ void convert_pairs(const float* __restrict__ src,
                              uint32_t* __restrict__ dh,
                              uint32_t* __restrict__ dl, int nwords)
{
    int i = blockIdx.x * blockDim.x + threadIdx.x;
    if (2 * i >= nwords) return;
    float4 v = *(const float4*)(src + 4 * (size_t)i);
    uint32_t h0, l0, h1, l1;
    split2(v.x, v.y, h0, l0);
    split2(v.z, v.w, h1, l1);
    *(uint2*)(dh + 2 * (size_t)i) = make_uint2(h0, h1);
    *(uint2*)(dl + 2 * (size_t)i) = make_uint2(l0, l1);
}

__global__ void bias_copy(const float* __restrict__ m1, const float* __restrict__ d1,
                          const float* __restrict__ m2, const float* __restrict__ d2,
                          float* __restrict__ o1, float* __restrict__ o2)
{
    int i = blockIdx.x * blockDim.x + threadIdx.x;
    if (i < 4 * 4096) {
        int b = i >> 12, k = i & 4095;
        o1[i] = (b == 0) ? m1[k] : d1[(b - 1) * 4096 + k];
    } else if (i < 4 * 4096 + 4 * 2560) {
        int j = i - 4 * 4096;
        int b = j / 2560, k = j % 2560;
        o2[j] = (b == 0) ? m2[k] : d2[(b - 1) * 2560 + k];
    }
}

// ---------------- GEMM: 64x64 tile, 128 threads, 3-stage (R11 proven) -------
// flags: bit0 residual, bit1 gelu, bit2 write pairs, bit3 write fp32 C,
//        bit4 dup fp32 to C2, bit5 fused qkv rope/vt epilogue,
//        bit6 add pos-table (Cres = pos_table)
#define SW 20
#define T_WORDS (64 * SW)
#define STG_WORDS (4 * T_WORDS)
#define NSTAGE 3
#define GEMM_SMEM (NSTAGE * STG_WORDS * 4)

__global__ void __launch_bounds__(128, 3) gemm_pre(
    const uint32_t* __restrict__ Ah, const uint32_t* __restrict__ Al,
    const uint32_t* __restrict__ Bh, const uint32_t* __restrict__ Bl,
    const float* __restrict__ bias, const float* __restrict__ Cres,
    float* __restrict__ C, uint32_t* __restrict__ Ch, uint32_t* __restrict__ Cl,
    float* __restrict__ C2, int M, int N, int K, int flags,
    int bsAw, int bsBw, int bsBias, int bsCE)
{
    extern __shared__ uint32_t sm[];
    const int bz = blockIdx.z;
    Ah += (size_t)bz * bsAw;  Al += (size_t)bz * bsAw;
    Bh += (size_t)bz * bsBw;  Bl += (size_t)bz * bsBw;
    bias += (size_t)bz * bsBias;
    C  += (size_t)bz * bsCE;
    C2 += (size_t)bz * bsCE;
    Ch += (size_t)bz * (bsCE >> 1);
    Cl += (size_t)bz * (bsCE >> 1);

    const int bm = blockIdx.y * 64, bn = blockIdx.x * 64;
    const int tid = threadIdx.x;
    const int wid = tid >> 5, lane = tid & 31;
    const int wm = wid;
    const int Kw = K >> 1;
    const int NT = Kw >> 4;

    float acc[8][4];
#pragma unroll
    for (int j = 0; j < 8; j++)
#pragma unroll
        for (int c = 0; c < 4; c++) acc[j][c] = 0.f;

    const uint32_t smbase = smem_u32(sm);

    const int aRow  = lane & 15;
    const int aColw = (lane >> 4) << 2;
    const int bRow  = (lane & 7) + ((lane & 16) ? 8 : 0);
    const int bColw = (lane & 8) ? 4 : 0;

#define LOAD_SLAB(stagebase_, kwo_) do {                                       \
    _Pragma("unroll")                                                          \
    for (int it = 0; it < 8; it++) {                                           \
        int idx = tid + it * 128;                                              \
        int arr = idx >> 8, r = (idx >> 2) & 63, c = idx & 3;                  \
        uint32_t smoff = (uint32_t)(arr * T_WORDS + r * SW + c * 4);           \
        const uint32_t* gp;                                                    \
        if (arr == 0)      gp = Ah + (size_t)(bm + r) * Kw + (kwo_) + c * 4;   \
        else if (arr == 1) gp = Al + (size_t)(bm + r) * Kw + (kwo_) + c * 4;   \
        else if (arr == 2) gp = Bh + (size_t)(bn + r) * Kw + (kwo_) + c * 4;   \
        else               gp = Bl + (size_t)(bn + r) * Kw + (kwo_) + c * 4;   \
        CP_ASYNC16((stagebase_) + smoff * 4, gp);                              \
    }                                                                          \
} while (0)

    LOAD_SLAB(smbase, 0);
    CP_COMMIT;
    if (NT > 1) LOAD_SLAB(smbase + STG_WORDS * 4, 16);
    CP_COMMIT;

    for (int kt = 0; kt < NT; kt++) {
        const int s = kt % NSTAGE;
        CP_WAIT1;
        __syncthreads();

        if (kt + 2 < NT) {
            const uint32_t stb = smbase + ((kt + 2) % NSTAGE) * STG_WORDS * 4;
            LOAD_SLAB(stb, (kt + 2) * 16);
        }
        CP_COMMIT;

        const uint32_t base   = smbase + (uint32_t)(s * STG_WORDS) * 4;
        const uint32_t baseAh = base;
        const uint32_t baseAl = base + (uint32_t)T_WORDS * 4;
        const uint32_t baseBh = base + (uint32_t)(2 * T_WORDS) * 4;
        const uint32_t baseBl = base + (uint32_t)(3 * T_WORDS) * 4;

#pragma unroll
        for (int ks = 0; ks < 2; ks++) {
            uint32_t ah[4], al[4];
            {
                uint32_t off = (uint32_t)((wm * 16 + aRow) * SW + ks * 8 + aColw) * 4;
                LDSM_X4(ah, baseAh + off);
                LDSM_X4(al, baseAl + off);
            }
            uint32_t bh[4][4], bl[4][4];
#pragma unroll
            for (int jj = 0; jj < 4; jj++) {
                uint32_t off = (uint32_t)((jj * 16 + bRow) * SW + ks * 8 + bColw) * 4;
                LDSM_X4(bh[jj], baseBh + off);
                LDSM_X4(bl[jj], baseBl + off);
            }
#pragma unroll
            for (int jj = 0; jj < 4; jj++)
#pragma unroll
                for (int jp = 0; jp < 2; jp++)
                    MMA_BF16(acc[jj*2+jp], ah, bh[jj][jp*2], bh[jj][jp*2+1]);
#pragma unroll
            for (int jj = 0; jj < 4; jj++)
#pragma unroll
                for (int jp = 0; jp < 2; jp++)
                    MMA_BF16(acc[jj*2+jp], ah, bl[jj][jp*2], bl[jj][jp*2+1]);
#pragma unroll
            for (int jj = 0; jj < 4; jj++)
#pragma unroll
                for (int jp = 0; jp < 2; jp++)
                    MMA_BF16(acc[jj*2+jp], al, bh[jj][jp*2], bh[jj][jp*2+1]);
        }
    }

    if (flags & 32) {
        // ---- fused qkv epilogue: rope q/k + v transpose, bias only ----
        const int r0 = bm + wm * 16 + (lane >> 2);
        const int colbase = bn;
        const int region = colbase >> 10;
        const int h = (colbase & 1023) >> 6;
#pragma unroll
        for (int half = 0; half < 2; half++) {
            const int t = r0 + half * 8;
            float vals[8][2];
#pragma unroll
            for (int j = 0; j < 8; j++) {
                int col = colbase + j * 8 + (lane & 3) * 2;
                vals[j][0] = acc[j][half * 2 + 0] + bias[col];
                vals[j][1] = acc[j][half * 2 + 1] + bias[col + 1];
            }
            if (region < 2) {
                uint32_t* Oh = region ? g_kh : g_qh;
                uint32_t* Ol = region ? g_kl : g_ql;
                const float qs = region ? 1.0f : 0.125f;
                const size_t ob = ((size_t)(h << 10) + t) * 32;
#pragma unroll
                for (int j = 0; j < 4; j++) {
                    int d = j * 8 + (lane & 3) * 2;
                    float c0 = g_cos[t*64 + d],      s0 = g_sin[t*64 + d];
                    float c1 = g_cos[t*64 + d + 1],  s1 = g_sin[t*64 + d + 1];
                    float c2 = g_cos[t*64 + d + 32], s2 = g_sin[t*64 + d + 32];
                    float c3 = g_cos[t*64 + d + 33], s3 = g_sin[t*64 + d + 33];
                    float x1a = vals[j][0],     x1b = vals[j][1];
                    float x2a = vals[j + 4][0], x2b = vals[j + 4][1];
                    uint32_t hh, ll;
                    split2((x1a*c0 - x2a*s0) * qs, (x1b*c1 - x2b*s1) * qs, hh, ll);
                    Oh[ob + (d >> 1)] = hh;  Ol[ob + (d >> 1)] = ll;
                    split2((x2a*c2 + x1a*s2) * qs, (x2b*c3 + x1b*s3) * qs, hh, ll);
                    Oh[ob + (d >> 1) + 16] = hh;  Ol[ob + (d >> 1) + 16] = ll;
                }
            } else {
                const int tp = t >> 1;
#pragma unroll
                for (int j = 0; j < 8; j++) {
                    float p0 = __shfl_down_sync(0xFFFFFFFFu, vals[j][0], 4);
                    float p1 = __shfl_down_sync(0xFFFFFFFFu, vals[j][1], 4);
                    if ((lane & 4) == 0) {
                        int d = j * 8 + (lane & 3) * 2;
                        uint32_t hh, ll;
                        split2(vals[j][0], p0, hh, ll);
                        g_vth[(size_t)(h * 64 + d) * 512 + tp] = hh;
                        g_vtl[(size_t)(h * 64 + d) * 512 + tp] = ll;
                        split2(vals[j][1], p1, hh, ll);
                        g_vth[(size_t)(h * 64 + d + 1) * 512 + tp] = hh;
                        g_vtl[(size_t)(h * 64 + d + 1) * 512 + tp] = ll;
                    }
                }
            }
        }
        return;
    }

    // standard epilogue
    {
        const int r0 = bm + wm * 16 + (lane >> 2);
#pragma unroll
        for (int j = 0; j < 8; j++) {
            int col = bn + j * 8 + (lane & 3) * 2;
            float b0 = bias[col], b1 = bias[col + 1];
#pragma unroll
            for (int half = 0; half < 2; half++) {
                int row = r0 + half * 8;
                float v0 = acc[j][half * 2 + 0] + b0;
                float v1 = acc[j][half * 2 + 1] + b1;
                if (flags & 2) { v0 = gelu_exact(v0); v1 = gelu_exact(v1); }
                if (flags & 1) {
                    const float* R = Cres + (size_t)row * N + col;
                    v0 += R[0]; v1 += R[1];
                }
                if (flags & 64) {
                    int bhh = row >> 6, rr = row & 63;
                    int pid = ((bhh * 2 + ((rr >> 1) & 1)) * 48)
                              + ((rr >> 2) * 2 + (rr & 1));
                    const float* P = Cres + (size_t)pid * DIM + col;
                    v0 += P[0]; v1 += P[1];
                }
                if (flags & 8)
                    *(float2*)(C + (size_t)row * N + col) = make_float2(v0, v1);
                if (flags & 16)
                    *(float2*)(C2 + (size_t)row * N + col) = make_float2(v0, v1);
                if (flags & 4) {
                    uint32_t hh, ll;
                    split2(v0, v1, hh, ll);
                    Ch[(size_t)row * (N >> 1) + (col >> 1)] = hh;
                    Cl[(size_t)row * (N >> 1) + (col >> 1)] = ll;
                }
            }
        }
    }
#undef LOAD_SLAB
}

// ---------------- LayerNorm -> hi/lo pairs ----------------------------------
__global__ void __launch_bounds__(256) ln_pairs(
    const float* __restrict__ x, const float* __restrict__ s,
    const float* __restrict__ b, uint32_t* __restrict__ yh,
    uint32_t* __restrict__ yl, int W)
{
    __shared__ float red[9];
    const int row = blockIdx.x;
    const int tid = threadIdx.x;
    const float* xr = x + (size_t)row * W;

    float sum = 0.f;
    for (int i = tid; i < W; i += 256) sum += xr[i];
#pragma unroll
    for (int o = 16; o > 0; o >>= 1) sum += __shfl_xor_sync(~0u, sum, o);
    if ((tid & 31) == 0) red[tid >> 5] = sum;
    __syncthreads();
    if (tid == 0) {
        float t = 0.f;
        for (int w = 0; w < 8; w++) t += red[w];
        red[8] = t;
    }
    __syncthreads();
    const float mu = red[8] / (float)W;

    float var = 0.f;
    for (int i = tid; i < W; i += 256) { float d = xr[i] - mu; var += d * d; }
    __syncthreads();
#pragma unroll
    for (int o = 16; o > 0; o >>= 1) var += __shfl_xor_sync(~0u, var, o);
    if ((tid & 31) == 0) red[tid >> 5] = var;
    __syncthreads();
    if (tid == 0) {
        float t = 0.f;
        for (int w = 0; w < 8; w++) t += red[w];
        red[8] = t;
    }
    __syncthreads();
    const float inv = rsqrtf(red[8] / (float)W + 1e-6f);

    const int Ww = W >> 1;
    for (int i = tid; i < Ww; i += 256) {
        float v0 = (xr[2*i]   - mu) * inv * s[2*i]   + b[2*i];
        float v1 = (xr[2*i+1] - mu) * inv * s[2*i+1] + b[2*i+1];
        uint32_t hh, ll;
        split2(v0, v1, hh, ll);
        yh[(size_t)row * Ww + i] = hh;
        yl[(size_t)row * Ww + i] = ll;
    }
}

// ---------------- RoPE table init -------------------------------------------
__global__ void init_rope(float* __restrict__ cosT, float* __restrict__ sinT)
{
    int idx = blockIdx.x * blockDim.x + threadIdx.x;
    if (idx >= SEQ * HD) return;
    int t = idx >> 6, d = idx & 63;
    int bh = t >> 6, r = t & 63, bw = r >> 2, ih = (r >> 1) & 1, iw = r & 1;
    float hp = (float)(bh * 2 + ih);
    float wp = (float)(bw * 2 + iw);
    int base = d & 31;
    float pos, inv;
    if (base < 16) { pos = hp; inv = powf(10000.f, -(float)base / 16.f); }
    else           { pos = wp; inv = powf(10000.f, -(float)(base - 16) / 16.f); }
    float ang = pos * inv;
    cosT[idx] = cosf(ang);
    sinT[idx] = sinf(ang);
}

// ---------------- tensor-core flash attention (64-q tiles, 128 thr) ---------
__global__ void __launch_bounds__(128) attn_mma(
    const uint32_t* __restrict__ qh, const uint32_t* __restrict__ ql,
    const uint32_t* __restrict__ kh, const uint32_t* __restrict__ kl,
    const uint32_t* __restrict__ vth, const uint32_t* __restrict__ vtl,
    uint32_t* __restrict__ oh, uint32_t* __restrict__ ol)
{
    __shared__ uint32_t sKh[64*33], sKl[64*33], sVh[64*33], sVl[64*33];
    const int h = blockIdx.y, qt = blockIdx.x;
    const int tid = threadIdx.x, w = tid >> 5, lane = tid & 31;
    const int gq = lane >> 2, l4 = lane & 3;
    const int qrow = qt * 64 + w * 16 + gq;

    uint32_t qfh[4][4], qfl[4][4];
    {
        const uint32_t* bh = qh + ((size_t)(h << 10) + qrow) * 32;
        const uint32_t* bl = ql + ((size_t)(h << 10) + qrow) * 32;
#pragma unroll
        for (int ks = 0; ks < 4; ks++) {
            int kp = ks * 8 + l4;
            qfh[ks][0] = bh[kp];        qfh[ks][1] = bh[8*32 + kp];
            qfh[ks][2] = bh[kp + 4];    qfh[ks][3] = bh[8*32 + kp + 4];
            qfl[ks][0] = bl[kp];        qfl[ks][1] = bl[8*32 + kp];
            qfl[ks][2] = bl[kp + 4];    qfl[ks][3] = bl[8*32 + kp + 4];
        }
    }

    float m0 = -1e30f, m1 = -1e30f, L0 = 0.f, L1 = 0.f;
    float O[8][4];
#pragma unroll
    for (int j = 0; j < 8; j++)
#pragma unroll
        for (int c = 0; c < 4; c++) O[j][c] = 0.f;

    for (int kt = 0; kt < SEQ; kt += 64) {
        __syncthreads();
        {
            const uint32_t* Kh = kh + ((size_t)(h << 10) + kt) * 32;
            const uint32_t* Kl = kl + ((size_t)(h << 10) + kt) * 32;
            const uint32_t* Vh = vth + (size_t)(h * 64) * 512 + (kt >> 1);
            const uint32_t* Vl = vtl + (size_t)(h * 64) * 512 + (kt >> 1);
            for (int u = tid; u < 64 * 32; u += 128) {
                int r = u >> 5, c = u & 31;
                sKh[r * 33 + c] = Kh[r * 32 + c];
                sKl[r * 33 + c] = Kl[r * 32 + c];
                sVh[r * 33 + c] = Vh[(size_t)r * 512 + c];
                sVl[r * 33 + c] = Vl[(size_t)r * 512 + c];
            }
        }
        __syncthreads();

        float sacc[8][4];
#pragma unroll
        for (int j = 0; j < 8; j++) {
            sacc[j][0] = sacc[j][1] = sacc[j][2] = sacc[j][3] = 0.f;
            int n = j * 8 + gq;
#pragma unroll
            for (int ks = 0; ks < 4; ks++) {
                int kp = ks * 8 + l4;
                uint32_t bh0 = sKh[n * 33 + kp], bh1 = sKh[n * 33 + kp + 4];
                uint32_t bl0 = sKl[n * 33 + kp], bl1 = sKl[n * 33 + kp + 4];
                MMA_BF16(sacc[j], qfh[ks], bh0, bh1);
                MMA_BF16(sacc[j], qfh[ks], bl0, bl1);
                MMA_BF16(sacc[j], qfl[ks], bh0, bh1);
            }
        }

        float mt0 = -1e30f, mt1 = -1e30f;
#pragma unroll
        for (int j = 0; j < 8; j++) {
            mt0 = fmaxf(mt0, fmaxf(sacc[j][0], sacc[j][1]));
            mt1 = fmaxf(mt1, fmaxf(sacc[j][2], sacc[j][3]));
        }
        mt0 = fmaxf(mt0, __shfl_xor_sync(~0u, mt0, 1));
        mt0 = fmaxf(mt0, __shfl_xor_sync(~0u, mt0, 2));
        mt1 = fmaxf(mt1, __shfl_xor_sync(~0u, mt1, 1));
        mt1 = fmaxf(mt1, __shfl_xor_sync(~0u, mt1, 2));
        float mn0 = fmaxf(m0, mt0), mn1 = fmaxf(m1, mt1);
        float sc0 = __expf(m0 - mn0), sc1 = __expf(m1 - mn1);
        float ls0 = 0.f, ls1 = 0.f;
#pragma unroll
        for (int j = 0; j < 8; j++) {
            sacc[j][0] = __expf(sacc[j][0] - mn0);
            sacc[j][1] = __expf(sacc[j][1] - mn0);
            sacc[j][2] = __expf(sacc[j][2] - mn1);
            sacc[j][3] = __expf(sacc[j][3] - mn1);
            ls0 += sacc[j][0] + sacc[j][1];
            ls1 += sacc[j][2] + sacc[j][3];
        }
        ls0 += __shfl_xor_sync(~0u, ls0, 1);
        ls0 += __shfl_xor_sync(~0u, ls0, 2);
        ls1 += __shfl_xor_sync(~0u, ls1, 1);
        ls1 += __shfl_xor_sync(~0u, ls1, 2);
        L0 = L0 * sc0 + ls0;
        L1 = L1 * sc1 + ls1;
        m0 = mn0; m1 = mn1;
#pragma unroll
        for (int j = 0; j < 8; j++) {
            O[j][0] *= sc0; O[j][1] *= sc0;
            O[j][2] *= sc1; O[j][3] *= sc1;
        }

        uint32_t pfh[4][4], pfl[4][4];
#pragma unroll
        for (int ks2 = 0; ks2 < 4; ks2++) {
            int j0 = 2 * ks2, j1 = j0 + 1;
            split2(sacc[j0][0], sacc[j0][1], pfh[ks2][0], pfl[ks2][0]);
            split2(sacc[j0][2], sacc[j0][3], pfh[ks2][1], pfl[ks2][1]);
            split2(sacc[j1][0], sacc[j1][1], pfh[ks2][2], pfl[ks2][2]);
            split2(sacc[j1][2], sacc[j1][3], pfh[ks2][3], pfl[ks2][3]);
        }

#pragma unroll
        for (int jd = 0; jd < 8; jd++) {
            int n = jd * 8 + gq;
#pragma unroll
            for (int ks2 = 0; ks2 < 4; ks2++) {
                int kp = ks2 * 8 + l4;
                uint32_t bh0 = sVh[n * 33 + kp], bh1 = sVh[n * 33 + kp + 4];
                uint32_t bl0 = sVl[n * 33 + kp], bl1 = sVl[n * 33 + kp + 4];
                MMA_BF16(O[jd], pfh[ks2], bh0, bh1);
                MMA_BF16(O[jd], pfh[ks2], bl0, bl1);
                MMA_BF16(O[jd], pfl[ks2], bh0, bh1);
            }
        }
    }

    float inv0 = 1.0f / L0, inv1 = 1.0f / L1;
#pragma unroll
    for (int jd = 0; jd < 8; jd++) {
        int word = h * 32 + jd * 4 + l4;
        uint32_t hh, ll;
        split2(O[jd][0] * inv0, O[jd][1] * inv0, hh, ll);
        oh[(size_t)qrow * 512 + word] = hh;
        ol[(size_t)qrow * 512 + word] = ll;
        split2(O[jd][2] * inv1, O[jd][3] * inv1, hh, ll);
        oh[(size_t)(qrow + 8) * 512 + word] = hh;
        ol[(size_t)(qrow + 8) * 512 + word] = ll;
    }
}

// ---------------- launch -----------------------------------------------------
extern "C" void kernel_launch(void* const* d_in, const int* in_sizes, int n_in,
                              void* d_out, int out_size)
{
    (void)in_sizes; (void)n_in; (void)out_size;
    const float* pixel     = (const float*)d_in[0];
    const float* conv_w    = (const float*)d_in[1];
    const float* conv_b    = (const float*)d_in[2];
    const float* pos_table = (const float*)d_in[3];
    const float* ln1_s     = (const float*)d_in[4];
    const float* ln1_b     = (const float*)d_in[5];
    const float* ln2_s     = (const float*)d_in[6];
    const float* ln2_b     = (const float*)d_in[7];
    const float* qkv_w     = (const float*)d_in[8];
    const float* qkv_b     = (const float*)d_in[9];
    const float* proj_w    = (const float*)d_in[10];
    const float* proj_b    = (const float*)d_in[11];
    const float* fc1_w     = (const float*)d_in[12];
    const float* fc1_b     = (const float*)d_in[13];
    const float* fc2_w     = (const float*)d_in[14];
    const float* fc2_b     = (const float*)d_in[15];
    const float* mrg_ln_s  = (const float*)d_in[16];
    const float* mrg_ln_b  = (const float*)d_in[17];
    const float* mrg_fc1_w = (const float*)d_in[18];
    const float* mrg_fc1_b = (const float*)d_in[19];
    const float* mrg_fc2_w = (const float*)d_in[20];
    const float* mrg_fc2_b = (const float*)d_in[21];
    const float* ds_ln_s   = (const float*)d_in[22];
    const float* ds_ln_b   = (const float*)d_in[23];
    const float* ds_fc1_w  = (const float*)d_in[24];
    const float* ds_fc1_b  = (const float*)d_in[25];
    const float* ds_fc2_w  = (const float*)d_in[26];
    const float* ds_fc2_b  = (const float*)d_in[27];
    float* out = (float*)d_out;

    uint32_t *wh, *wl, *hh, *hl, *ah, *al, *fh, *fl, *ph, *pl;
    uint32_t *qhp, *qlp, *khp, *klp, *vth, *vtl;
    uint32_t *mh, *ml, *mfh, *mfl;
    float *x, *ds, *cosT, *sinT, *mb1, *mb2;
    cudaGetSymbolAddress((void**)&wh,  g_wh);
    cudaGetSymbolAddress((void**)&wl,  g_wl);
    cudaGetSymbolAddress((void**)&hh,  g_hh);
    cudaGetSymbolAddress((void**)&hl,  g_hl);
    cudaGetSymbolAddress((void**)&ah,  g_ah);
    cudaGetSymbolAddress((void**)&al,  g_al);
    cudaGetSymbolAddress((void**)&fh,  g_fh);
    cudaGetSymbolAddress((void**)&fl,  g_fl);
    cudaGetSymbolAddress((void**)&ph,  g_ph);
    cudaGetSymbolAddress((void**)&pl,  g_pl);
    cudaGetSymbolAddress((void**)&qhp, g_qh);
    cudaGetSymbolAddress((void**)&qlp, g_ql);
    cudaGetSymbolAddress((void**)&khp, g_kh);
    cudaGetSymbolAddress((void**)&klp, g_kl);
    cudaGetSymbolAddress((void**)&vth, g_vth);
    cudaGetSymbolAddress((void**)&vtl, g_vtl);
    cudaGetSymbolAddress((void**)&mh,  g_mh);
    cudaGetSymbolAddress((void**)&ml,  g_ml);
    cudaGetSymbolAddress((void**)&mfh, g_mfh);
    cudaGetSymbolAddress((void**)&mfl, g_mfl);
    cudaGetSymbolAddress((void**)&x,    g_x);
    cudaGetSymbolAddress((void**)&ds,   g_ds);
    cudaGetSymbolAddress((void**)&cosT, g_cos);
    cudaGetSymbolAddress((void**)&sinT, g_sin);
    cudaGetSymbolAddress((void**)&mb1,  g_mb1);
    cudaGetSymbolAddress((void**)&mb2,  g_mb2);

    cudaFuncSetAttribute(gemm_pre,
                         cudaFuncAttributeMaxDynamicSharedMemorySize, GEMM_SMEM);

    // ---- single merged weight-conversion launch ----
    CvtTable tab;
    const float* srcs[9] = { conv_w, qkv_w, proj_w, fc1_w, fc2_w,
                             mrg_fc1_w, ds_fc1_w, mrg_fc2_w, ds_fc2_w };
    const uint32_t offs[9] = { W_CONV, W_QKV, W_PROJ, W_FC1, W_FC2,
                               W_MFC1, W_DFC1, W_MFC2, W_DFC2 };
    const uint32_t nws[9] = { W_QKV - W_CONV, W_PROJ - W_QKV, W_FC1 - W_PROJ,
                              W_FC2 - W_FC1, W_MFC1 - W_FC2, W_DFC1 - W_MFC1,
                              W_MFC2 - W_DFC1, W_DFC2 - W_MFC2, W_TOTAL - W_DFC2 };
    uint32_t blk = 0;
    for (int c = 0; c < 9; c++) {
        tab.src[c] = srcs[c];
        tab.dstoff[c] = offs[c];
        tab.blkstart[c] = blk;
        blk += nws[c] >> 9;
    }
    tab.blkstart[9] = blk;
    convert_all<<<blk, 256>>>(tab, wh, wl);
    convert_pairs<<<(SEQ * 768 / 2 + 255) / 256, 256>>>(pixel, ph, pl, SEQ * 768);
    init_rope<<<(SEQ * HD + 255) / 256, 256>>>(cosT, sinT);

    // patch embed + fused pos add
    gemm_pre<<<dim3(DIM / 64, SEQ / 64), 128, GEMM_SMEM>>>(
        ph, pl, wh + W_CONV, wl + W_CONV, conv_b, pos_table, x, nullptr, nullptr,
        nullptr, SEQ, DIM, 1536, 8 | 64, 0, 0, 0, 0);

    for (int i = 0; i < DEPTH; i++) {
        ln_pairs<<<SEQ, 256>>>(x, ln1_s + i * DIM, ln1_b + i * DIM, hh, hl, DIM);
        gemm_pre<<<dim3(3 * DIM / 64, SEQ / 64), 128, GEMM_SMEM>>>(
            hh, hl, wh + W_QKV + (size_t)i * (3 * DIM * DIM / 2),
            wl + W_QKV + (size_t)i * (3 * DIM * DIM / 2),
            qkv_b + (size_t)i * 3 * DIM, nullptr, nullptr, nullptr, nullptr,
            nullptr, SEQ, 3 * DIM, DIM, 32, 0, 0, 0, 0);
        attn_mma<<<dim3(SEQ / 64, NHEAD), 128>>>(qhp, qlp, khp, klp, vth, vtl, ah, al);
        gemm_pre<<<dim3(DIM / 64, SEQ / 64), 128, GEMM_SMEM>>>(
            ah, al, wh + W_PROJ + (size_t)i * (DIM * DIM / 2),
            wl + W_PROJ + (size_t)i * (DIM * DIM / 2),
            proj_b + (size_t)i * DIM, x, x, nullptr, nullptr,
            nullptr, SEQ, DIM, DIM, 1 | 8, 0, 0, 0, 0);
        ln_pairs<<<SEQ, 256>>>(x, ln2_s + i * DIM, ln2_b + i * DIM, hh, hl, DIM);
        gemm_pre<<<dim3(FFD / 64, SEQ / 64), 128, GEMM_SMEM>>>(
            hh, hl, wh + W_FC1 + (size_t)i * (FFD * DIM / 2),
            wl + W_FC1 + (size_t)i * (FFD * DIM / 2),
            fc1_b + (size_t)i * FFD, nullptr, nullptr, fh, fl,
            nullptr, SEQ, FFD, DIM, 2 | 4, 0, 0, 0, 0);

        int fc2_flags = 1 | 8;
        float* dup = nullptr;
        if (i == 5)  { fc2_flags |= 16; dup = ds; }
        if (i == 11) { fc2_flags |= 16; dup = ds + SEQ * DIM; }
        if (i == 17) { fc2_flags |= 16; dup = ds + 2 * SEQ * DIM; }
        if (i == 23) { fc2_flags |= 16; dup = out; }
        gemm_pre<<<dim3(DIM / 64, SEQ / 64), 128, GEMM_SMEM>>>(
            fh, fl, wh + W_FC2 + (size_t)i * (DIM * FFD / 2),
            wl + W_FC2 + (size_t)i * (DIM * FFD / 2),
            fc2_b + (size_t)i * DIM, x, x, nullptr, nullptr,
            dup, SEQ, DIM, FFD, fc2_flags, 0, 0, 0, 0);

        if (i == 0)
            bias_copy<<<104, 256>>>(mrg_fc1_b, ds_fc1_b, mrg_fc2_b, ds_fc2_b, mb1, mb2);
    }

    // ---- batched mergers: batch 0 = pooled, 1..3 = deepstack ----
    ln_pairs<<<SEQ, 256>>>(x, mrg_ln_s, mrg_ln_b, mh, ml, DIM);
    for (int j = 0; j < 3; j++)
        ln_pairs<<<256, 256>>>(ds + (size_t)j * SEQ * DIM,
                               ds_ln_s + j * 4096, ds_ln_b + j * 4096,
                               mh + (size_t)(j + 1) * 524288,
                               ml + (size_t)(j + 1) * 524288, 4096);
    gemm_pre<<<dim3(4096 / 64, 256 / 64, 4), 128, GEMM_SMEM>>>(
        mh, ml, wh + W_MFC1, wl + W_MFC1, mb1, nullptr, nullptr, mfh, mfl,
        nullptr, 256, 4096, 4096, 2 | 4,
        524288, 8388608, 4096, 1048576);
    gemm_pre<<<dim3(OUTD / 64, 256 / 64, 4), 128, GEMM_SMEM>>>(
        mfh, mfl, wh + W_MFC2, wl + W_MFC2, mb2, nullptr, out + SEQ * DIM,
        nullptr, nullptr, nullptr, 256, OUTD, 4096, 8,
        524288, 5242880, 2560, 655360);
}

// round 14
// speedup vs baseline: 1.1212x; 1.0555x over previous
#include <cuda_runtime.h>
#include <cuda_bf16.h>
#include <math.h>
#include <stdint.h>

#define SEQ   1024
#define DIM   1024
#define NHEAD 16
#define HD    64
#define FFD   4096
#define DEPTH 24
#define OUTD  2560
#define KVSPL 4

// ---------------- weight hi/lo pools (uint32 = bf16x2 pair along K) --------
#define W_CONV   0u
#define W_QKV    786432u
#define W_PROJ   38535168u
#define W_FC1    51118080u
#define W_FC2    101449728u
#define W_MFC1   151781376u
#define W_DFC1   160169984u
#define W_MFC2   185335808u
#define W_DFC2   190578688u
#define W_TOTAL  206307328u

__device__ __align__(16) uint32_t g_wh[W_TOTAL];
__device__ __align__(16) uint32_t g_wl[W_TOTAL];

// ---------------- activation scratch ----------------------------------------
__device__ float g_x   [SEQ*DIM];
__device__ float g_cos [SEQ*HD];
__device__ float g_sin [SEQ*HD];
__device__ __align__(16) uint32_t g_hh [SEQ*DIM/2];
__device__ __align__(16) uint32_t g_hl [SEQ*DIM/2];
__device__ __align__(16) uint32_t g_ah [SEQ*DIM/2];
__device__ __align__(16) uint32_t g_al [SEQ*DIM/2];
__device__ __align__(16) uint32_t g_fh [SEQ*FFD/2];
__device__ __align__(16) uint32_t g_fl [SEQ*FFD/2];
__device__ __align__(16) uint32_t g_ph [SEQ*1536/2];
__device__ __align__(16) uint32_t g_pl [SEQ*1536/2];
__device__ __align__(16) uint32_t g_qh [NHEAD*SEQ*32];
__device__ __align__(16) uint32_t g_ql [NHEAD*SEQ*32];
__device__ __align__(16) uint32_t g_kh [NHEAD*SEQ*32];
__device__ __align__(16) uint32_t g_kl [NHEAD*SEQ*32];
__device__ __align__(16) uint32_t g_vth[NHEAD*HD*512];
__device__ __align__(16) uint32_t g_vtl[NHEAD*HD*512];
__device__ float g_ds  [3*SEQ*DIM];
__device__ __align__(16) uint32_t g_mh [4*524288];
__device__ __align__(16) uint32_t g_ml [4*524288];
__device__ __align__(16) uint32_t g_mfh[4*524288];
__device__ __align__(16) uint32_t g_mfl[4*524288];
__device__ float g_mb1[4*4096];
__device__ float g_mb2[4*2560];
// split-KV attention scratch
__device__ __align__(16) float g_oacc[KVSPL*NHEAD*SEQ*HD];   // 16 MB
__device__ float g_mL[KVSPL*NHEAD*SEQ*2];

__device__ __forceinline__ float gelu_exact(float x) {
    return 0.5f * x * (1.0f + erff(x * 0.70710678118654752f));
}

__device__ __forceinline__ void split2(float x, float y, uint32_t& hi, uint32_t& lo) {
    __nv_bfloat16 xh = __float2bfloat16(x);
    __nv_bfloat16 yh = __float2bfloat16(y);
    __nv_bfloat16 xl = __float2bfloat16(x - __bfloat162float(xh));
    __nv_bfloat16 yl = __float2bfloat16(y - __bfloat162float(yh));
    __nv_bfloat162 h2 = __halves2bfloat162(xh, yh);
    __nv_bfloat162 l2 = __halves2bfloat162(xl, yl);
    hi = *(uint32_t*)&h2;
    lo = *(uint32_t*)&l2;
}

#define MMA_BF16(d, a, b0, b1)                                                 \
    asm volatile("mma.sync.aligned.m16n8k16.row.col.f32.bf16.bf16.f32 "        \
                 "{%0,%1,%2,%3},{%4,%5,%6,%7},{%8,%9},{%0,%1,%2,%3};"          \
                 : "+f"(d[0]), "+f"(d[1]), "+f"(d[2]), "+f"(d[3])              \
                 : "r"(a[0]), "r"(a[1]), "r"(a[2]), "r"(a[3]), "r"(b0), "r"(b1))

#define LDSM_X4(r, addr)                                                       \
    asm volatile("ldmatrix.sync.aligned.m8n8.x4.shared.b16 {%0,%1,%2,%3},[%4];"\
                 : "=r"((r)[0]), "=r"((r)[1]), "=r"((r)[2]), "=r"((r)[3])      \
                 : "r"(addr))

#define CP_ASYNC16(dst, src)                                                   \
    asm volatile("cp.async.cg.shared.global [%0],[%1],16;" :: "r"(dst), "l"(src))
#define CP_COMMIT  asm volatile("cp.async.commit_group;")
#define CP_WAIT1   asm volatile("cp.async.wait_group 1;")

__device__ __forceinline__ uint32_t smem_u32(const void* p) {
    return (uint32_t)__cvta_generic_to_shared(p);
}

// ---------------- merged fp32 -> bf16 hi/lo conversion -----------------------
struct CvtTable {
    const float* src[9];
    uint32_t dstoff[9];
    uint32_t blkstart[10];
};

__global__ void convert_all(CvtTable tab, uint32_t* __restrict__ dh,
                            uint32_t* __restrict__ dl)
{
    int bid = blockIdx.x;
    int c = 0;
    while (bid >= (int)tab.blkstart[c + 1]) c++;
    size_t p = (size_t)(bid - tab.blkstart[c]) * 256 + threadIdx.x;
    const float* s = tab.src[c];
    float4 v = *(const float4*)(s + 4 * p);
    uint32_t h0, l0, h1, l1;
    split2(v.x, v.y, h0, l0);
    split2(v.z, v.w, h1, l1);
    size_t o = tab.dstoff[c] + 2 * p;
    *(uint2*)(dh + o) = make_uint2(h0, h1);
    *(uint2*)(dl + o) = make_uint2(l0, l1);
}

__global__ void convert_pairs(const float* __restrict__ src,
                              uint32_t* __restrict__ dh,
                              uint32_t* __restrict__ dl, int nwords)
{
    int i = blockIdx.x * blockDim.x + threadIdx.x;
    if (2 * i >= nwords) return;
    float4 v = *(const float4*)(src + 4 * (size_t)i);
    uint32_t h0, l0, h1, l1;
    split2(v.x, v.y, h0, l0);
    split2(v.z, v.w, h1, l1);
    *(uint2*)(dh + 2 * (size_t)i) = make_uint2(h0, h1);
    *(uint2*)(dl + 2 * (size_t)i) = make_uint2(l0, l1);
}

__global__ void bias_copy(const float* __restrict__ m1, const float* __restrict__ d1,
                          const float* __restrict__ m2, const float* __restrict__ d2,
                          float* __restrict__ o1, float* __restrict__ o2)
{
    int i = blockIdx.x * blockDim.x + threadIdx.x;
    if (i < 4 * 4096) {
        int b = i >> 12, k = i & 4095;
        o1[i] = (b == 0) ? m1[k] : d1[(b - 1) * 4096 + k];
    } else if (i < 4 * 4096 + 4 * 2560) {
        int j = i - 4 * 4096;
        int b = j / 2560, k = j % 2560;
        o2[j] = (b == 0) ? m2[k] : d2[(b - 1) * 2560 + k];
    }
}

// ---------------- GEMM: 64x64 tile, 128 threads, 3-stage (proven) -----------
#define SW 20
#define T_WORDS (64 * SW)
#define STG_WORDS (4 * T_WORDS)
#define NSTAGE 3
#define GEMM_SMEM (NSTAGE * STG_WORDS * 4)

__global__ void __launch_bounds__(128, 3) gemm_pre(
    const uint32_t* __restrict__ Ah, const uint32_t* __restrict__ Al,
    const uint32_t* __restrict__ Bh, const uint32_t* __restrict__ Bl,
    const float* __restrict__ bias, const float* __restrict__ Cres,
    float* __restrict__ C, uint32_t* __restrict__ Ch, uint32_t* __restrict__ Cl,
    float* __restrict__ C2, int M, int N, int K, int flags,
    int bsAw, int bsBw, int bsBias, int bsCE)
{
    extern __shared__ uint32_t sm[];
    const int bz = blockIdx.z;
    Ah += (size_t)bz * bsAw;  Al += (size_t)bz * bsAw;
    Bh += (size_t)bz * bsBw;  Bl += (size_t)bz * bsBw;
    bias += (size_t)bz * bsBias;
    C  += (size_t)bz * bsCE;
    C2 += (size_t)bz * bsCE;
    Ch += (size_t)bz * (bsCE >> 1);
    Cl += (size_t)bz * (bsCE >> 1);

    const int bm = blockIdx.y * 64, bn = blockIdx.x * 64;
    const int tid = threadIdx.x;
    const int wid = tid >> 5, lane = tid & 31;
    const int wm = wid;
    const int Kw = K >> 1;
    const int NT = Kw >> 4;

    float acc[8][4];
#pragma unroll
    for (int j = 0; j < 8; j++)
#pragma unroll
        for (int c = 0; c < 4; c++) acc[j][c] = 0.f;

    const uint32_t smbase = smem_u32(sm);

    const int aRow  = lane & 15;
    const int aColw = (lane >> 4) << 2;
    const int bRow  = (lane & 7) + ((lane & 16) ? 8 : 0);
    const int bColw = (lane & 8) ? 4 : 0;

#define LOAD_SLAB(stagebase_, kwo_) do {                                       \
    _Pragma("unroll")                                                          \
    for (int it = 0; it < 8; it++) {                                           \
        int idx = tid + it * 128;                                              \
        int arr = idx >> 8, r = (idx >> 2) & 63, c = idx & 3;                  \
        uint32_t smoff = (uint32_t)(arr * T_WORDS + r * SW + c * 4);           \
        const uint32_t* gp;                                                    \
        if (arr == 0)      gp = Ah + (size_t)(bm + r) * Kw + (kwo_) + c * 4;   \
        else if (arr == 1) gp = Al + (size_t)(bm + r) * Kw + (kwo_) + c * 4;   \
        else if (arr == 2) gp = Bh + (size_t)(bn + r) * Kw + (kwo_) + c * 4;   \
        else               gp = Bl + (size_t)(bn + r) * Kw + (kwo_) + c * 4;   \
        CP_ASYNC16((stagebase_) + smoff * 4, gp);                              \
    }                                                                          \
} while (0)

    LOAD_SLAB(smbase, 0);
    CP_COMMIT;
    if (NT > 1) LOAD_SLAB(smbase + STG_WORDS * 4, 16);
    CP_COMMIT;

    for (int kt = 0; kt < NT; kt++) {
        const int s = kt % NSTAGE;
        CP_WAIT1;
        __syncthreads();

        if (kt + 2 < NT) {
            const uint32_t stb = smbase + ((kt + 2) % NSTAGE) * STG_WORDS * 4;
            LOAD_SLAB(stb, (kt + 2) * 16);
        }
        CP_COMMIT;

        const uint32_t base   = smbase + (uint32_t)(s * STG_WORDS) * 4;
        const uint32_t baseAh = base;
        const uint32_t baseAl = base + (uint32_t)T_WORDS * 4;
        const uint32_t baseBh = base + (uint32_t)(2 * T_WORDS) * 4;
        const uint32_t baseBl = base + (uint32_t)(3 * T_WORDS) * 4;

#pragma unroll
        for (int ks = 0; ks < 2; ks++) {
            uint32_t ah[4], al[4];
            {
                uint32_t off = (uint32_t)((wm * 16 + aRow) * SW + ks * 8 + aColw) * 4;
                LDSM_X4(ah, baseAh + off);
                LDSM_X4(al, baseAl + off);
            }
            uint32_t bh[4][4], bl[4][4];
#pragma unroll
            for (int jj = 0; jj < 4; jj++) {
                uint32_t off = (uint32_t)((jj * 16 + bRow) * SW + ks * 8 + bColw) * 4;
                LDSM_X4(bh[jj], baseBh + off);
                LDSM_X4(bl[jj], baseBl + off);
            }
#pragma unroll
            for (int jj = 0; jj < 4; jj++)
#pragma unroll
                for (int jp = 0; jp < 2; jp++)
                    MMA_BF16(acc[jj*2+jp], ah, bh[jj][jp*2], bh[jj][jp*2+1]);
#pragma unroll
            for (int jj = 0; jj < 4; jj++)
#pragma unroll
                for (int jp = 0; jp < 2; jp++)
                    MMA_BF16(acc[jj*2+jp], ah, bl[jj][jp*2], bl[jj][jp*2+1]);
#pragma unroll
            for (int jj = 0; jj < 4; jj++)
#pragma unroll
                for (int jp = 0; jp < 2; jp++)
                    MMA_BF16(acc[jj*2+jp], al, bh[jj][jp*2], bh[jj][jp*2+1]);
        }
    }

    if (flags & 32) {
        // ---- fused qkv epilogue: rope q/k + v transpose, bias only ----
        const int r0 = bm + wm * 16 + (lane >> 2);
        const int colbase = bn;
        const int region = colbase >> 10;
        const int h = (colbase & 1023) >> 6;
#pragma unroll
        for (int half = 0; half < 2; half++) {
            const int t = r0 + half * 8;
            float vals[8][2];
#pragma unroll
            for (int j = 0; j < 8; j++) {
                int col = colbase + j * 8 + (lane & 3) * 2;
                vals[j][0] = acc[j][half * 2 + 0] + bias[col];
                vals[j][1] = acc[j][half * 2 + 1] + bias[col + 1];
            }
            if (region < 2) {
                uint32_t* Oh = region ? g_kh : g_qh;
                uint32_t* Ol = region ? g_kl : g_ql;
                const float qs = region ? 1.0f : 0.125f;
                const size_t ob = ((size_t)(h << 10) + t) * 32;
#pragma unroll
                for (int j = 0; j < 4; j++) {
                    int d = j * 8 + (lane & 3) * 2;
                    float c0 = g_cos[t*64 + d],      s0 = g_sin[t*64 + d];
                    float c1 = g_cos[t*64 + d + 1],  s1 = g_sin[t*64 + d + 1];
                    float c2 = g_cos[t*64 + d + 32], s2 = g_sin[t*64 + d + 32];
                    float c3 = g_cos[t*64 + d + 33], s3 = g_sin[t*64 + d + 33];
                    float x1a = vals[j][0],     x1b = vals[j][1];
                    float x2a = vals[j + 4][0], x2b = vals[j + 4][1];
                    uint32_t hh, ll;
                    split2((x1a*c0 - x2a*s0) * qs, (x1b*c1 - x2b*s1) * qs, hh, ll);
                    Oh[ob + (d >> 1)] = hh;  Ol[ob + (d >> 1)] = ll;
                    split2((x2a*c2 + x1a*s2) * qs, (x2b*c3 + x1b*s3) * qs, hh, ll);
                    Oh[ob + (d >> 1) + 16] = hh;  Ol[ob + (d >> 1) + 16] = ll;
                }
            } else {
                const int tp = t >> 1;
#pragma unroll
                for (int j = 0; j < 8; j++) {
                    float p0 = __shfl_down_sync(0xFFFFFFFFu, vals[j][0], 4);
                    float p1 = __shfl_down_sync(0xFFFFFFFFu, vals[j][1], 4);
                    if ((lane & 4) == 0) {
                        int d = j * 8 + (lane & 3) * 2;
                        uint32_t hh, ll;
                        split2(vals[j][0], p0, hh, ll);
                        g_vth[(size_t)(h * 64 + d) * 512 + tp] = hh;
                        g_vtl[(size_t)(h * 64 + d) * 512 + tp] = ll;
                        split2(vals[j][1], p1, hh, ll);
                        g_vth[(size_t)(h * 64 + d + 1) * 512 + tp] = hh;
                        g_vtl[(size_t)(h * 64 + d + 1) * 512 + tp] = ll;
                    }
                }
            }
        }
        return;
    }

    // standard epilogue
    {
        const int r0 = bm + wm * 16 + (lane >> 2);
#pragma unroll
        for (int j = 0; j < 8; j++) {
            int col = bn + j * 8 + (lane & 3) * 2;
            float b0 = bias[col], b1 = bias[col + 1];
#pragma unroll
            for (int half = 0; half < 2; half++) {
                int row = r0 + half * 8;
                float v0 = acc[j][half * 2 + 0] + b0;
                float v1 = acc[j][half * 2 + 1] + b1;
                if (flags & 2) { v0 = gelu_exact(v0); v1 = gelu_exact(v1); }
                if (flags & 1) {
                    const float* R = Cres + (size_t)row * N + col;
                    v0 += R[0]; v1 += R[1];
                }
                if (flags & 64) {
                    int bhh = row >> 6, rr = row & 63;
                    int pid = ((bhh * 2 + ((rr >> 1) & 1)) * 48)
                              + ((rr >> 2) * 2 + (rr & 1));
                    const float* P = Cres + (size_t)pid * DIM + col;
                    v0 += P[0]; v1 += P[1];
                }
                if (flags & 8)
                    *(float2*)(C + (size_t)row * N + col) = make_float2(v0, v1);
                if (flags & 16)
                    *(float2*)(C2 + (size_t)row * N + col) = make_float2(v0, v1);
                if (flags & 4) {
                    uint32_t hh, ll;
                    split2(v0, v1, hh, ll);
                    Ch[(size_t)row * (N >> 1) + (col >> 1)] = hh;
                    Cl[(size_t)row * (N >> 1) + (col >> 1)] = ll;
                }
            }
        }
    }
#undef LOAD_SLAB
}

// ---------------- LayerNorm -> hi/lo pairs ----------------------------------
__global__ void __launch_bounds__(256) ln_pairs(
    const float* __restrict__ x, const float* __restrict__ s,
    const float* __restrict__ b, uint32_t* __restrict__ yh,
    uint32_t* __restrict__ yl, int W)
{
    __shared__ float red[9];
    const int row = blockIdx.x;
    const int tid = threadIdx.x;
    const float* xr = x + (size_t)row * W;

    float sum = 0.f;
    for (int i = tid; i < W; i += 256) sum += xr[i];
#pragma unroll
    for (int o = 16; o > 0; o >>= 1) sum += __shfl_xor_sync(~0u, sum, o);
    if ((tid & 31) == 0) red[tid >> 5] = sum;
    __syncthreads();
    if (tid == 0) {
        float t = 0.f;
        for (int w = 0; w < 8; w++) t += red[w];
        red[8] = t;
    }
    __syncthreads();
    const float mu = red[8] / (float)W;

    float var = 0.f;
    for (int i = tid; i < W; i += 256) { float d = xr[i] - mu; var += d * d; }
    __syncthreads();
#pragma unroll
    for (int o = 16; o > 0; o >>= 1) var += __shfl_xor_sync(~0u, var, o);
    if ((tid & 31) == 0) red[tid >> 5] = var;
    __syncthreads();
    if (tid == 0) {
        float t = 0.f;
        for (int w = 0; w < 8; w++) t += red[w];
        red[8] = t;
    }
    __syncthreads();
    const float inv = rsqrtf(red[8] / (float)W + 1e-6f);

    const int Ww = W >> 1;
    for (int i = tid; i < Ww; i += 256) {
        float v0 = (xr[2*i]   - mu) * inv * s[2*i]   + b[2*i];
        float v1 = (xr[2*i+1] - mu) * inv * s[2*i+1] + b[2*i+1];
        uint32_t hh, ll;
        split2(v0, v1, hh, ll);
        yh[(size_t)row * Ww + i] = hh;
        yl[(size_t)row * Ww + i] = ll;
    }
}

// ---------------- RoPE table init -------------------------------------------
__global__ void init_rope(float* __restrict__ cosT, float* __restrict__ sinT)
{
    int idx = blockIdx.x * blockDim.x + threadIdx.x;
    if (idx >= SEQ * HD) return;
    int t = idx >> 6, d = idx & 63;
    int bh = t >> 6, r = t & 63, bw = r >> 2, ih = (r >> 1) & 1, iw = r & 1;
    float hp = (float)(bh * 2 + ih);
    float wp = (float)(bw * 2 + iw);
    int base = d & 31;
    float pos, inv;
    if (base < 16) { pos = hp; inv = powf(10000.f, -(float)base / 16.f); }
    else           { pos = wp; inv = powf(10000.f, -(float)(base - 16) / 16.f); }
    float ang = pos * inv;
    cosT[idx] = cosf(ang);
    sinT[idx] = sinf(ang);
}

// ---------------- split-KV flash attention (128q, 256thr, 4 splits) ---------
__global__ void __launch_bounds__(256) attn_mma(
    const uint32_t* __restrict__ qh, const uint32_t* __restrict__ ql,
    const uint32_t* __restrict__ kh, const uint32_t* __restrict__ kl,
    const uint32_t* __restrict__ vth, const uint32_t* __restrict__ vtl,
    float* __restrict__ oacc, float* __restrict__ mL)
{
    __shared__ uint32_t sKh[64*33], sKl[64*33], sVh[64*33], sVl[64*33];
    const int h = blockIdx.y, qt = blockIdx.x, z = blockIdx.z;
    const int tid = threadIdx.x, w = tid >> 5, lane = tid & 31;
    const int gq = lane >> 2, l4 = lane & 3;
    const int qrow = qt * 128 + w * 16 + gq;

    uint32_t qfh[4][4], qfl[4][4];
    {
        const uint32_t* bh = qh + ((size_t)(h << 10) + qrow) * 32;
        const uint32_t* bl = ql + ((size_t)(h << 10) + qrow) * 32;
#pragma unroll
        for (int ks = 0; ks < 4; ks++) {
            int kp = ks * 8 + l4;
            qfh[ks][0] = bh[kp];        qfh[ks][1] = bh[8*32 + kp];
            qfh[ks][2] = bh[kp + 4];    qfh[ks][3] = bh[8*32 + kp + 4];
            qfl[ks][0] = bl[kp];        qfl[ks][1] = bl[8*32 + kp];
            qfl[ks][2] = bl[kp + 4];    qfl[ks][3] = bl[8*32 + kp + 4];
        }
    }

    float m0 = -1e30f, m1 = -1e30f, L0 = 0.f, L1 = 0.f;
    float O[8][4];
#pragma unroll
    for (int j = 0; j < 8; j++)
#pragma unroll
        for (int c = 0; c < 4; c++) O[j][c] = 0.f;

    const int kt0 = z * (SEQ / KVSPL);
    for (int kt = kt0; kt < kt0 + SEQ / KVSPL; kt += 64) {
        __syncthreads();
        {
            const uint32_t* Kh = kh + ((size_t)(h << 10) + kt) * 32;
            const uint32_t* Kl = kl + ((size_t)(h << 10) + kt) * 32;
            const uint32_t* Vh = vth + (size_t)(h * 64) * 512 + (kt >> 1);
            const uint32_t* Vl = vtl + (size_t)(h * 64) * 512 + (kt >> 1);
            for (int u = tid; u < 64 * 32; u += 256) {
                int r = u >> 5, c = u & 31;
                sKh[r * 33 + c] = Kh[r * 32 + c];
                sKl[r * 33 + c] = Kl[r * 32 + c];
                sVh[r * 33 + c] = Vh[(size_t)r * 512 + c];
                sVl[r * 33 + c] = Vl[(size_t)r * 512 + c];
            }
        }
        __syncthreads();

        float sacc[8][4];
#pragma unroll
        for (int j = 0; j < 8; j++) {
            sacc[j][0] = sacc[j][1] = sacc[j][2] = sacc[j][3] = 0.f;
            int n = j * 8 + gq;
#pragma unroll
            for (int ks = 0; ks < 4; ks++) {
                int kp = ks * 8 + l4;
                uint32_t bh0 = sKh[n * 33 + kp], bh1 = sKh[n * 33 + kp + 4];
                uint32_t bl0 = sKl[n * 33 + kp], bl1 = sKl[n * 33 + kp + 4];
                MMA_BF16(sacc[j], qfh[ks], bh0, bh1);
                MMA_BF16(sacc[j], qfh[ks], bl0, bl1);
                MMA_BF16(sacc[j], qfl[ks], bh0, bh1);
            }
        }

        float mt0 = -1e30f, mt1 = -1e30f;
#pragma unroll
        for (int j = 0; j < 8; j++) {
            mt0 = fmaxf(mt0, fmaxf(sacc[j][0], sacc[j][1]));
            mt1 = fmaxf(mt1, fmaxf(sacc[j][2], sacc[j][3]));
        }
        mt0 = fmaxf(mt0, __shfl_xor_sync(~0u, mt0, 1));
        mt0 = fmaxf(mt0, __shfl_xor_sync(~0u, mt0, 2));
        mt1 = fmaxf(mt1, __shfl_xor_sync(~0u, mt1, 1));
        mt1 = fmaxf(mt1, __shfl_xor_sync(~0u, mt1, 2));
        float mn0 = fmaxf(m0, mt0), mn1 = fmaxf(m1, mt1);
        float sc0 = __expf(m0 - mn0), sc1 = __expf(m1 - mn1);
        float ls0 = 0.f, ls1 = 0.f;
#pragma unroll
        for (int j = 0; j < 8; j++) {
            sacc[j][0] = __expf(sacc[j][0] - mn0);
            sacc[j][1] = __expf(sacc[j][1] - mn0);
            sacc[j][2] = __expf(sacc[j][2] - mn1);
            sacc[j][3] = __expf(sacc[j][3] - mn1);
            ls0 += sacc[j][0] + sacc[j][1];
            ls1 += sacc[j][2] + sacc[j][3];
        }
        ls0 += __shfl_xor_sync(~0u, ls0, 1);
        ls0 += __shfl_xor_sync(~0u, ls0, 2);
        ls1 += __shfl_xor_sync(~0u, ls1, 1);
        ls1 += __shfl_xor_sync(~0u, ls1, 2);
        L0 = L0 * sc0 + ls0;
        L1 = L1 * sc1 + ls1;
        m0 = mn0; m1 = mn1;
#pragma unroll
        for (int j = 0; j < 8; j++) {
            O[j][0] *= sc0; O[j][1] *= sc0;
            O[j][2] *= sc1; O[j][3] *= sc1;
        }

        uint32_t pfh[4][4], pfl[4][4];
#pragma unroll
        for (int ks2 = 0; ks2 < 4; ks2++) {
            int j0 = 2 * ks2, j1 = j0 + 1;
            split2(sacc[j0][0], sacc[j0][1], pfh[ks2][0], pfl[ks2][0]);
            split2(sacc[j0][2], sacc[j0][3], pfh[ks2][1], pfl[ks2][1]);
            split2(sacc[j1][0], sacc[j1][1], pfh[ks2][2], pfl[ks2][2]);
            split2(sacc[j1][2], sacc[j1][3], pfh[ks2][3], pfl[ks2][3]);
        }

        // note: V tile rows in smem correspond to kt..kt+63; column index within
        // smem uses (kt - kt0) offset? No: sVh holds 32 word-cols = this tile's
        // 64 tokens; P fragment k-index ks2*16.. matches tile-local tokens.
#pragma unroll
        for (int jd = 0; jd < 8; jd++) {
            int n = jd * 8 + gq;
#pragma unroll
            for (int ks2 = 0; ks2 < 4; ks2++) {
                int kp = ks2 * 8 + l4;
                uint32_t bh0 = sVh[n * 33 + kp], bh1 = sVh[n * 33 + kp + 4];
                uint32_t bl0 = sVl[n * 33 + kp], bl1 = sVl[n * 33 + kp + 4];
                MMA_BF16(O[jd], pfh[ks2], bh0, bh1);
                MMA_BF16(O[jd], pfh[ks2], bl0, bl1);
                MMA_BF16(O[jd], pfl[ks2], bh0, bh1);
            }
        }
    }

    // write unnormalized partials + (m, L)
    float* ob0 = oacc + (((size_t)(z * NHEAD + h) * SEQ + qrow) * 64);
    float* ob1 = oacc + (((size_t)(z * NHEAD + h) * SEQ + qrow + 8) * 64);
#pragma unroll
    for (int jd = 0; jd < 8; jd++) {
        int d = jd * 8 + l4 * 2;
        *(float2*)(ob0 + d) = make_float2(O[jd][0], O[jd][1]);
        *(float2*)(ob1 + d) = make_float2(O[jd][2], O[jd][3]);
    }
    if (l4 == 0) {
        size_t mb = ((size_t)(z * NHEAD + h) * SEQ + qrow) * 2;
        mL[mb] = m0;  mL[mb + 1] = L0;
        mb = ((size_t)(z * NHEAD + h) * SEQ + qrow + 8) * 2;
        mL[mb] = m1;  mL[mb + 1] = L1;
    }
}

// ---------------- combine split-KV partials -> hi/lo pairs -------------------
__global__ void attn_combine(const float* __restrict__ oacc,
                             const float* __restrict__ mL,
                             uint32_t* __restrict__ oh, uint32_t* __restrict__ ol)
{
    int idx = blockIdx.x * blockDim.x + threadIdx.x;   // [t][h][dp] 1024*16*32
    if (idx >= SEQ * NHEAD * 32) return;
    int dp = idx & 31, h = (idx >> 5) & 15, t = idx >> 9;

    float m[KVSPL], L[KVSPL];
    float mstar = -1e30f;
#pragma unroll
    for (int z = 0; z < KVSPL; z++) {
        size_t mb = ((size_t)(z * NHEAD + h) * SEQ + t) * 2;
        m[z] = mL[mb];  L[z] = mL[mb + 1];
        mstar = fmaxf(mstar, m[z]);
    }
    float Lsum = 0.f, o0 = 0.f, o1 = 0.f;
#pragma unroll
    for (int z = 0; z < KVSPL; z++) {
        float wz = __expf(m[z] - mstar);
        Lsum += L[z] * wz;
        const float* ob = oacc + (((size_t)(z * NHEAD + h) * SEQ + t) * 64 + dp * 2);
        o0 += ob[0] * wz;
        o1 += ob[1] * wz;
    }
    float inv = 1.0f / Lsum;
    uint32_t hh, ll;
    split2(o0 * inv, o1 * inv, hh, ll);
    oh[(size_t)t * 512 + h * 32 + dp] = hh;
    ol[(size_t)t * 512 + h * 32 + dp] = ll;
}

// ---------------- launch -----------------------------------------------------
extern "C" void kernel_launch(void* const* d_in, const int* in_sizes, int n_in,
                              void* d_out, int out_size)
{
    (void)in_sizes; (void)n_in; (void)out_size;
    const float* pixel     = (const float*)d_in[0];
    const float* conv_w    = (const float*)d_in[1];
    const float* conv_b    = (const float*)d_in[2];
    const float* pos_table = (const float*)d_in[3];
    const float* ln1_s     = (const float*)d_in[4];
    const float* ln1_b     = (const float*)d_in[5];
    const float* ln2_s     = (const float*)d_in[6];
    const float* ln2_b     = (const float*)d_in[7];
    const float* qkv_w     = (const float*)d_in[8];
    const float* qkv_b     = (const float*)d_in[9];
    const float* proj_w    = (const float*)d_in[10];
    const float* proj_b    = (const float*)d_in[11];
    const float* fc1_w     = (const float*)d_in[12];
    const float* fc1_b     = (const float*)d_in[13];
    const float* fc2_w     = (const float*)d_in[14];
    const float* fc2_b     = (const float*)d_in[15];
    const float* mrg_ln_s  = (const float*)d_in[16];
    const float* mrg_ln_b  = (const float*)d_in[17];
    const float* mrg_fc1_w = (const float*)d_in[18];
    const float* mrg_fc1_b = (const float*)d_in[19];
    const float* mrg_fc2_w = (const float*)d_in[20];
    const float* mrg_fc2_b = (const float*)d_in[21];
    const float* ds_ln_s   = (const float*)d_in[22];
    const float* ds_ln_b   = (const float*)d_in[23];
    const float* ds_fc1_w  = (const float*)d_in[24];
    const float* ds_fc1_b  = (const float*)d_in[25];
    const float* ds_fc2_w  = (const float*)d_in[26];
    const float* ds_fc2_b  = (const float*)d_in[27];
    float* out = (float*)d_out;

    uint32_t *wh, *wl, *hh, *hl, *ah, *al, *fh, *fl, *ph, *pl;
    uint32_t *qhp, *qlp, *khp, *klp, *vth, *vtl;
    uint32_t *mh, *ml, *mfh, *mfl;
    float *x, *ds, *cosT, *sinT, *mb1, *mb2, *oacc, *mLp;
    cudaGetSymbolAddress((void**)&wh,  g_wh);
    cudaGetSymbolAddress((void**)&wl,  g_wl);
    cudaGetSymbolAddress((void**)&hh,  g_hh);
    cudaGetSymbolAddress((void**)&hl,  g_hl);
    cudaGetSymbolAddress((void**)&ah,  g_ah);
    cudaGetSymbolAddress((void**)&al,  g_al);
    cudaGetSymbolAddress((void**)&fh,  g_fh);
    cudaGetSymbolAddress((void**)&fl,  g_fl);
    cudaGetSymbolAddress((void**)&ph,  g_ph);
    cudaGetSymbolAddress((void**)&pl,  g_pl);
    cudaGetSymbolAddress((void**)&qhp, g_qh);
    cudaGetSymbolAddress((void**)&qlp, g_ql);
    cudaGetSymbolAddress((void**)&khp, g_kh);
    cudaGetSymbolAddress((void**)&klp, g_kl);
    cudaGetSymbolAddress((void**)&vth, g_vth);
    cudaGetSymbolAddress((void**)&vtl, g_vtl);
    cudaGetSymbolAddress((void**)&mh,  g_mh);
    cudaGetSymbolAddress((void**)&ml,  g_ml);
    cudaGetSymbolAddress((void**)&mfh, g_mfh);
    cudaGetSymbolAddress((void**)&mfl, g_mfl);
    cudaGetSymbolAddress((void**)&x,    g_x);
    cudaGetSymbolAddress((void**)&ds,   g_ds);
    cudaGetSymbolAddress((void**)&cosT, g_cos);
    cudaGetSymbolAddress((void**)&sinT, g_sin);
    cudaGetSymbolAddress((void**)&mb1,  g_mb1);
    cudaGetSymbolAddress((void**)&mb2,  g_mb2);
    cudaGetSymbolAddress((void**)&oacc, g_oacc);
    cudaGetSymbolAddress((void**)&mLp,  g_mL);

    cudaFuncSetAttribute(gemm_pre,
                         cudaFuncAttributeMaxDynamicSharedMemorySize, GEMM_SMEM);

    // ---- single merged weight-conversion launch ----
    CvtTable tab;
    const float* srcs[9] = { conv_w, qkv_w, proj_w, fc1_w, fc2_w,
                             mrg_fc1_w, ds_fc1_w, mrg_fc2_w, ds_fc2_w };
    const uint32_t offs[9] = { W_CONV, W_QKV, W_PROJ, W_FC1, W_FC2,
                               W_MFC1, W_DFC1, W_MFC2, W_DFC2 };
    const uint32_t nws[9] = { W_QKV - W_CONV, W_PROJ - W_QKV, W_FC1 - W_PROJ,
                              W_FC2 - W_FC1, W_MFC1 - W_FC2, W_DFC1 - W_MFC1,
                              W_MFC2 - W_DFC1, W_DFC2 - W_MFC2, W_TOTAL - W_DFC2 };
    uint32_t blk = 0;
    for (int c = 0; c < 9; c++) {
        tab.src[c] = srcs[c];
        tab.dstoff[c] = offs[c];
        tab.blkstart[c] = blk;
        blk += nws[c] >> 9;
    }
    tab.blkstart[9] = blk;
    convert_all<<<blk, 256>>>(tab, wh, wl);
    convert_pairs<<<(SEQ * 768 / 2 + 255) / 256, 256>>>(pixel, ph, pl, SEQ * 768);
    init_rope<<<(SEQ * HD + 255) / 256, 256>>>(cosT, sinT);

    // patch embed + fused pos add
    gemm_pre<<<dim3(DIM / 64, SEQ / 64), 128, GEMM_SMEM>>>(
        ph, pl, wh + W_CONV, wl + W_CONV, conv_b, pos_table, x, nullptr, nullptr,
        nullptr, SEQ, DIM, 1536, 8 | 64, 0, 0, 0, 0);

    for (int i = 0; i < DEPTH; i++) {
        ln_pairs<<<SEQ, 256>>>(x, ln1_s + i * DIM, ln1_b + i * DIM, hh, hl, DIM);
        gemm_pre<<<dim3(3 * DIM / 64, SEQ / 64), 128, GEMM_SMEM>>>(
            hh, hl, wh + W_QKV + (size_t)i * (3 * DIM * DIM / 2),
            wl + W_QKV + (size_t)i * (3 * DIM * DIM / 2),
            qkv_b + (size_t)i * 3 * DIM, nullptr, nullptr, nullptr, nullptr,
            nullptr, SEQ, 3 * DIM, DIM, 32, 0, 0, 0, 0);
        attn_mma<<<dim3(SEQ / 128, NHEAD, KVSPL), 256>>>(qhp, qlp, khp, klp,
                                                         vth, vtl, oacc, mLp);
        attn_combine<<<(SEQ * NHEAD * 32) / 256, 256>>>(oacc, mLp, ah, al);
        gemm_pre<<<dim3(DIM / 64, SEQ / 64), 128, GEMM_SMEM>>>(
            ah, al, wh + W_PROJ + (size_t)i * (DIM * DIM / 2),
            wl + W_PROJ + (size_t)i * (DIM * DIM / 2),
            proj_b + (size_t)i * DIM, x, x, nullptr, nullptr,
            nullptr, SEQ, DIM, DIM, 1 | 8, 0, 0, 0, 0);
        ln_pairs<<<SEQ, 256>>>(x, ln2_s + i * DIM, ln2_b + i * DIM, hh, hl, DIM);
        gemm_pre<<<dim3(FFD / 64, SEQ / 64), 128, GEMM_SMEM>>>(
            hh, hl, wh + W_FC1 + (size_t)i * (FFD * DIM / 2),
            wl + W_FC1 + (size_t)i * (FFD * DIM / 2),
            fc1_b + (size_t)i * FFD, nullptr, nullptr, fh, fl,
            nullptr, SEQ, FFD, DIM, 2 | 4, 0, 0, 0, 0);

        int fc2_flags = 1 | 8;
        float* dup = nullptr;
        if (i == 5)  { fc2_flags |= 16; dup = ds; }
        if (i == 11) { fc2_flags |= 16; dup = ds + SEQ * DIM; }
        if (i == 17) { fc2_flags |= 16; dup = ds + 2 * SEQ * DIM; }
        if (i == 23) { fc2_flags |= 16; dup = out; }
        gemm_pre<<<dim3(DIM / 64, SEQ / 64), 128, GEMM_SMEM>>>(
            fh, fl, wh + W_FC2 + (size_t)i * (DIM * FFD / 2),
            wl + W_FC2 + (size_t)i * (DIM * FFD / 2),
            fc2_b + (size_t)i * DIM, x, x, nullptr, nullptr,
            dup, SEQ, DIM, FFD, fc2_flags, 0, 0, 0, 0);

        if (i == 0)
            bias_copy<<<104, 256>>>(mrg_fc1_b, ds_fc1_b, mrg_fc2_b, ds_fc2_b, mb1, mb2);
    }

    // ---- batched mergers: batch 0 = pooled, 1..3 = deepstack ----
    ln_pairs<<<SEQ, 256>>>(x, mrg_ln_s, mrg_ln_b, mh, ml, DIM);
    for (int j = 0; j < 3; j++)
        ln_pairs<<<256, 256>>>(ds + (size_t)j * SEQ * DIM,
                               ds_ln_s + j * 4096, ds_ln_b + j * 4096,
                               mh + (size_t)(j + 1) * 524288,
                               ml + (size_t)(j + 1) * 524288, 4096);
    gemm_pre<<<dim3(4096 / 64, 256 / 64, 4), 128, GEMM_SMEM>>>(
        mh, ml, wh + W_MFC1, wl + W_MFC1, mb1, nullptr, nullptr, mfh, mfl,
        nullptr, 256, 4096, 4096, 2 | 4,
        524288, 8388608, 4096, 1048576);
    gemm_pre<<<dim3(OUTD / 64, 256 / 64, 4), 128, GEMM_SMEM>>>(
        mfh, mfl, wh + W_MFC2, wl + W_MFC2, mb2, nullptr, out + SEQ * DIM,
        nullptr, nullptr, nullptr, 256, OUTD, 4096, 8,
        524288, 5242880, 2560, 655360);
}

// round 15
// speedup vs baseline: 1.1263x; 1.0046x over previous
#include <cuda_runtime.h>
#include <cuda_bf16.h>
#include <cuda_fp16.h>
#include <math.h>
#include <stdint.h>

#define SEQ   1024
#define DIM   1024
#define NHEAD 16
#define HD    64
#define FFD   4096
#define DEPTH 24
#define OUTD  2560
#define KVSPL 4

// ---------------- weight hi/lo pools (uint32 = bf16x2 pair along K) --------
#define W_CONV   0u
#define W_QKV    786432u
#define W_PROJ   38535168u
#define W_FC1    51118080u
#define W_FC2    101449728u
#define W_MFC1   151781376u
#define W_DFC1   160169984u
#define W_MFC2   185335808u
#define W_DFC2   190578688u
#define W_TOTAL  206307328u

__device__ __align__(16) uint32_t g_wh[W_TOTAL];
__device__ __align__(16) uint32_t g_wl[W_TOTAL];

// ---------------- activation scratch ----------------------------------------
__device__ float g_x   [SEQ*DIM];
__device__ float g_cos [SEQ*HD];
__device__ float g_sin [SEQ*HD];
__device__ __align__(16) uint32_t g_hh [SEQ*DIM/2];
__device__ __align__(16) uint32_t g_hl [SEQ*DIM/2];
__device__ __align__(16) uint32_t g_ah [SEQ*DIM/2];
__device__ __align__(16) uint32_t g_al [SEQ*DIM/2];
__device__ __align__(16) uint32_t g_fh [SEQ*FFD/2];
__device__ __align__(16) uint32_t g_fl [SEQ*FFD/2];
__device__ __align__(16) uint32_t g_ph [SEQ*1536/2];
__device__ __align__(16) uint32_t g_pl [SEQ*1536/2];
__device__ __align__(16) uint32_t g_qh [NHEAD*SEQ*32];
__device__ __align__(16) uint32_t g_ql [NHEAD*SEQ*32];
__device__ __align__(16) uint32_t g_kh [NHEAD*SEQ*32];
__device__ __align__(16) uint32_t g_kl [NHEAD*SEQ*32];
__device__ __align__(16) uint32_t g_vth[NHEAD*HD*512];   // V^T f16 hi pairs
__device__ __align__(16) uint32_t g_vtl[NHEAD*HD*512];   // V^T f16 lo pairs
__device__ float g_ds  [3*SEQ*DIM];
__device__ __align__(16) uint32_t g_mh [4*524288];
__device__ __align__(16) uint32_t g_ml [4*524288];
__device__ __align__(16) uint32_t g_mfh[4*524288];
__device__ __align__(16) uint32_t g_mfl[4*524288];
__device__ float g_mb1[4*4096];
__device__ float g_mb2[4*2560];
__device__ __align__(16) float g_oacc[KVSPL*NHEAD*SEQ*HD];
__device__ float g_mL[KVSPL*NHEAD*SEQ*2];

__device__ __forceinline__ float gelu_exact(float x) {
    return 0.5f * x * (1.0f + erff(x * 0.70710678118654752f));
}

__device__ __forceinline__ void split2(float x, float y, uint32_t& hi, uint32_t& lo) {
    __nv_bfloat16 xh = __float2bfloat16(x);
    __nv_bfloat16 yh = __float2bfloat16(y);
    __nv_bfloat16 xl = __float2bfloat16(x - __bfloat162float(xh));
    __nv_bfloat16 yl = __float2bfloat16(y - __bfloat162float(yh));
    __nv_bfloat162 h2 = __halves2bfloat162(xh, yh);
    __nv_bfloat162 l2 = __halves2bfloat162(xl, yl);
    hi = *(uint32_t*)&h2;
    lo = *(uint32_t*)&l2;
}

// f16 hi/lo split (for V)
__device__ __forceinline__ void split2h(float x, float y, uint32_t& hi, uint32_t& lo) {
    __half xh = __float2half_rn(x);
    __half yh = __float2half_rn(y);
    __half xl = __float2half_rn(x - __half2float(xh));
    __half yl = __float2half_rn(y - __half2float(yh));
    __half2 h2 = __halves2half2(xh, yh);
    __half2 l2 = __halves2half2(xl, yl);
    hi = *(uint32_t*)&h2;
    lo = *(uint32_t*)&l2;
}

// packed f16x2 exp2: returns packed P, also accumulates fp32 sum
__device__ __forceinline__ uint32_t pexp2(float a0, float a1, float& sum) {
    __half2 h = __floats2half2_rn(a0, a1);
    uint32_t hu = *(uint32_t*)&h;
    uint32_t r;
    asm("ex2.approx.f16x2 %0, %1;" : "=r"(r) : "r"(hu));
    __half2 p = *(__half2*)&r;
    float2 pf = __half22float2(p);
    sum += pf.x + pf.y;
    return r;
}

#define MMA_BF16(d, a, b0, b1)                                                 \
    asm volatile("mma.sync.aligned.m16n8k16.row.col.f32.bf16.bf16.f32 "        \
                 "{%0,%1,%2,%3},{%4,%5,%6,%7},{%8,%9},{%0,%1,%2,%3};"          \
                 : "+f"(d[0]), "+f"(d[1]), "+f"(d[2]), "+f"(d[3])              \
                 : "r"(a[0]), "r"(a[1]), "r"(a[2]), "r"(a[3]), "r"(b0), "r"(b1))

#define MMA_F16(d, a, b0, b1)                                                  \
    asm volatile("mma.sync.aligned.m16n8k16.row.col.f32.f16.f16.f32 "          \
                 "{%0,%1,%2,%3},{%4,%5,%6,%7},{%8,%9},{%0,%1,%2,%3};"          \
                 : "+f"(d[0]), "+f"(d[1]), "+f"(d[2]), "+f"(d[3])              \
                 : "r"(a[0]), "r"(a[1]), "r"(a[2]), "r"(a[3]), "r"(b0), "r"(b1))

#define LDSM_X4(r, addr)                                                       \
    asm volatile("ldmatrix.sync.aligned.m8n8.x4.shared.b16 {%0,%1,%2,%3},[%4];"\
                 : "=r"((r)[0]), "=r"((r)[1]), "=r"((r)[2]), "=r"((r)[3])      \
                 : "r"(addr))

#define CP_ASYNC16(dst, src)                                                   \
    asm volatile("cp.async.cg.shared.global [%0],[%1],16;" :: "r"(dst), "l"(src))
#define CP_COMMIT  asm volatile("cp.async.commit_group;")
#define CP_WAIT1   asm volatile("cp.async.wait_group 1;")

__device__ __forceinline__ uint32_t smem_u32(const void* p) {
    return (uint32_t)__cvta_generic_to_shared(p);
}

// ---------------- merged fp32 -> bf16 hi/lo conversion -----------------------
struct CvtTable {
    const float* src[9];
    uint32_t dstoff[9];
    uint32_t blkstart[10];
};

__global__ void convert_all(CvtTable tab, uint32_t* __restrict__ dh,
                            uint32_t* __restrict__ dl)
{
    int bid = blockIdx.x;
    int c = 0;
    while (bid >= (int)tab.blkstart[c + 1]) c++;
    size_t p = (size_t)(bid - tab.blkstart[c]) * 256 + threadIdx.x;
    const float* s = tab.src[c];
    float4 v = *(const float4*)(s + 4 * p);
    uint32_t h0, l0, h1, l1;
    split2(v.x, v.y, h0, l0);
    split2(v.z, v.w, h1, l1);
    size_t o = tab.dstoff[c] + 2 * p;
    *(uint2*)(dh + o) = make_uint2(h0, h1);
    *(uint2*)(dl + o) = make_uint2(l0, l1);
}

__global__ void convert_pairs(const float* __restrict__ src,
                              uint32_t* __restrict__ dh,
                              uint32_t* __restrict__ dl, int nwords)
{
    int i = blockIdx.x * blockDim.x + threadIdx.x;
    if (2 * i >= nwords) return;
    float4 v = *(const float4*)(src + 4 * (size_t)i);
    uint32_t h0, l0, h1, l1;
    split2(v.x, v.y, h0, l0);
    split2(v.z, v.w, h1, l1);
    *(uint2*)(dh + 2 * (size_t)i) = make_uint2(h0, h1);
    *(uint2*)(dl + 2 * (size_t)i) = make_uint2(l0, l1);
}

__global__ void bias_copy(const float* __restrict__ m1, const float* __restrict__ d1,
                          const float* __restrict__ m2, const float* __restrict__ d2,
                          float* __restrict__ o1, float* __restrict__ o2)
{
    int i = blockIdx.x * blockDim.x + threadIdx.x;
    if (i < 4 * 4096) {
        int b = i >> 12, k = i & 4095;
        o1[i] = (b == 0) ? m1[k] : d1[(b - 1) * 4096 + k];
    } else if (i < 4 * 4096 + 4 * 2560) {
        int j = i - 4 * 4096;
        int b = j / 2560, k = j % 2560;
        o2[j] = (b == 0) ? m2[k] : d2[(b - 1) * 2560 + k];
    }
}

// ---------------- GEMM: 64x64 tile, 128 threads, 3-stage (proven) -----------
#define SW 20
#define T_WORDS (64 * SW)
#define STG_WORDS (4 * T_WORDS)
#define NSTAGE 3
#define GEMM_SMEM (NSTAGE * STG_WORDS * 4)

__global__ void __launch_bounds__(128, 3) gemm_pre(
    const uint32_t* __restrict__ Ah, const uint32_t* __restrict__ Al,
    const uint32_t* __restrict__ Bh, const uint32_t* __restrict__ Bl,
    const float* __restrict__ bias, const float* __restrict__ Cres,
    float* __restrict__ C, uint32_t* __restrict__ Ch, uint32_t* __restrict__ Cl,
    float* __restrict__ C2, int M, int N, int K, int flags,
    int bsAw, int bsBw, int bsBias, int bsCE)
{
    extern __shared__ uint32_t sm[];
    const int bz = blockIdx.z;
    Ah += (size_t)bz * bsAw;  Al += (size_t)bz * bsAw;
    Bh += (size_t)bz * bsBw;  Bl += (size_t)bz * bsBw;
    bias += (size_t)bz * bsBias;
    C  += (size_t)bz * bsCE;
    C2 += (size_t)bz * bsCE;
    Ch += (size_t)bz * (bsCE >> 1);
    Cl += (size_t)bz * (bsCE >> 1);

    const int bm = blockIdx.y * 64, bn = blockIdx.x * 64;
    const int tid = threadIdx.x;
    const int wid = tid >> 5, lane = tid & 31;
    const int wm = wid;
    const int Kw = K >> 1;
    const int NT = Kw >> 4;

    float acc[8][4];
#pragma unroll
    for (int j = 0; j < 8; j++)
#pragma unroll
        for (int c = 0; c < 4; c++) acc[j][c] = 0.f;

    const uint32_t smbase = smem_u32(sm);

    const int aRow  = lane & 15;
    const int aColw = (lane >> 4) << 2;
    const int bRow  = (lane & 7) + ((lane & 16) ? 8 : 0);
    const int bColw = (lane & 8) ? 4 : 0;

#define LOAD_SLAB(stagebase_, kwo_) do {                                       \
    _Pragma("unroll")                                                          \
    for (int it = 0; it < 8; it++) {                                           \
        int idx = tid + it * 128;                                              \
        int arr = idx >> 8, r = (idx >> 2) & 63, c = idx & 3;                  \
        uint32_t smoff = (uint32_t)(arr * T_WORDS + r * SW + c * 4);           \
        const uint32_t* gp;                                                    \
        if (arr == 0)      gp = Ah + (size_t)(bm + r) * Kw + (kwo_) + c * 4;   \
        else if (arr == 1) gp = Al + (size_t)(bm + r) * Kw + (kwo_) + c * 4;   \
        else if (arr == 2) gp = Bh + (size_t)(bn + r) * Kw + (kwo_) + c * 4;   \
        else               gp = Bl + (size_t)(bn + r) * Kw + (kwo_) + c * 4;   \
        CP_ASYNC16((stagebase_) + smoff * 4, gp);                              \
    }                                                                          \
} while (0)

    LOAD_SLAB(smbase, 0);
    CP_COMMIT;
    if (NT > 1) LOAD_SLAB(smbase + STG_WORDS * 4, 16);
    CP_COMMIT;

    for (int kt = 0; kt < NT; kt++) {
        const int s = kt % NSTAGE;
        CP_WAIT1;
        __syncthreads();

        if (kt + 2 < NT) {
            const uint32_t stb = smbase + ((kt + 2) % NSTAGE) * STG_WORDS * 4;
            LOAD_SLAB(stb, (kt + 2) * 16);
        }
        CP_COMMIT;

        const uint32_t base   = smbase + (uint32_t)(s * STG_WORDS) * 4;
        const uint32_t baseAh = base;
        const uint32_t baseAl = base + (uint32_t)T_WORDS * 4;
        const uint32_t baseBh = base + (uint32_t)(2 * T_WORDS) * 4;
        const uint32_t baseBl = base + (uint32_t)(3 * T_WORDS) * 4;

#pragma unroll
        for (int ks = 0; ks < 2; ks++) {
            uint32_t ah[4], al[4];
            {
                uint32_t off = (uint32_t)((wm * 16 + aRow) * SW + ks * 8 + aColw) * 4;
                LDSM_X4(ah, baseAh + off);
                LDSM_X4(al, baseAl + off);
            }
            uint32_t bh[4][4], bl[4][4];
#pragma unroll
            for (int jj = 0; jj < 4; jj++) {
                uint32_t off = (uint32_t)((jj * 16 + bRow) * SW + ks * 8 + bColw) * 4;
                LDSM_X4(bh[jj], baseBh + off);
                LDSM_X4(bl[jj], baseBl + off);
            }
#pragma unroll
            for (int jj = 0; jj < 4; jj++)
#pragma unroll
                for (int jp = 0; jp < 2; jp++)
                    MMA_BF16(acc[jj*2+jp], ah, bh[jj][jp*2], bh[jj][jp*2+1]);
#pragma unroll
            for (int jj = 0; jj < 4; jj++)
#pragma unroll
                for (int jp = 0; jp < 2; jp++)
                    MMA_BF16(acc[jj*2+jp], ah, bl[jj][jp*2], bl[jj][jp*2+1]);
#pragma unroll
            for (int jj = 0; jj < 4; jj++)
#pragma unroll
                for (int jp = 0; jp < 2; jp++)
                    MMA_BF16(acc[jj*2+jp], al, bh[jj][jp*2], bh[jj][jp*2+1]);
        }
    }

    if (flags & 32) {
        // ---- fused qkv epilogue: rope q/k + v transpose (f16 split) ----
        const int r0 = bm + wm * 16 + (lane >> 2);
        const int colbase = bn;
        const int region = colbase >> 10;
        const int h = (colbase & 1023) >> 6;
#pragma unroll
        for (int half = 0; half < 2; half++) {
            const int t = r0 + half * 8;
            float vals[8][2];
#pragma unroll
            for (int j = 0; j < 8; j++) {
                int col = colbase + j * 8 + (lane & 3) * 2;
                vals[j][0] = acc[j][half * 2 + 0] + bias[col];
                vals[j][1] = acc[j][half * 2 + 1] + bias[col + 1];
            }
            if (region < 2) {
                uint32_t* Oh = region ? g_kh : g_qh;
                uint32_t* Ol = region ? g_kl : g_ql;
                const float qs = region ? 1.0f : 0.125f;
                const size_t ob = ((size_t)(h << 10) + t) * 32;
#pragma unroll
                for (int j = 0; j < 4; j++) {
                    int d = j * 8 + (lane & 3) * 2;
                    float c0 = g_cos[t*64 + d],      s0 = g_sin[t*64 + d];
                    float c1 = g_cos[t*64 + d + 1],  s1 = g_sin[t*64 + d + 1];
                    float c2 = g_cos[t*64 + d + 32], s2 = g_sin[t*64 + d + 32];
                    float c3 = g_cos[t*64 + d + 33], s3 = g_sin[t*64 + d + 33];
                    float x1a = vals[j][0],     x1b = vals[j][1];
                    float x2a = vals[j + 4][0], x2b = vals[j + 4][1];
                    uint32_t hh, ll;
                    split2((x1a*c0 - x2a*s0) * qs, (x1b*c1 - x2b*s1) * qs, hh, ll);
                    Oh[ob + (d >> 1)] = hh;  Ol[ob + (d >> 1)] = ll;
                    split2((x2a*c2 + x1a*s2) * qs, (x2b*c3 + x1b*s3) * qs, hh, ll);
                    Oh[ob + (d >> 1) + 16] = hh;  Ol[ob + (d >> 1) + 16] = ll;
                }
            } else {
                const int tp = t >> 1;
#pragma unroll
                for (int j = 0; j < 8; j++) {
                    float p0 = __shfl_down_sync(0xFFFFFFFFu, vals[j][0], 4);
                    float p1 = __shfl_down_sync(0xFFFFFFFFu, vals[j][1], 4);
                    if ((lane & 4) == 0) {
                        int d = j * 8 + (lane & 3) * 2;
                        uint32_t hh, ll;
                        split2h(vals[j][0], p0, hh, ll);
                        g_vth[(size_t)(h * 64 + d) * 512 + tp] = hh;
                        g_vtl[(size_t)(h * 64 + d) * 512 + tp] = ll;
                        split2h(vals[j][1], p1, hh, ll);
                        g_vth[(size_t)(h * 64 + d + 1) * 512 + tp] = hh;
                        g_vtl[(size_t)(h * 64 + d + 1) * 512 + tp] = ll;
                    }
                }
            }
        }
        return;
    }

    // standard epilogue
    {
        const int r0 = bm + wm * 16 + (lane >> 2);
#pragma unroll
        for (int j = 0; j < 8; j++) {
            int col = bn + j * 8 + (lane & 3) * 2;
            float b0 = bias[col], b1 = bias[col + 1];
#pragma unroll
            for (int half = 0; half < 2; half++) {
                int row = r0 + half * 8;
                float v0 = acc[j][half * 2 + 0] + b0;
                float v1 = acc[j][half * 2 + 1] + b1;
                if (flags & 2) { v0 = gelu_exact(v0); v1 = gelu_exact(v1); }
                if (flags & 1) {
                    const float* R = Cres + (size_t)row * N + col;
                    v0 += R[0]; v1 += R[1];
                }
                if (flags & 64) {
                    int bhh = row >> 6, rr = row & 63;
                    int pid = ((bhh * 2 + ((rr >> 1) & 1)) * 48)
                              + ((rr >> 2) * 2 + (rr & 1));
                    const float* P = Cres + (size_t)pid * DIM + col;
                    v0 += P[0]; v1 += P[1];
                }
                if (flags & 8)
                    *(float2*)(C + (size_t)row * N + col) = make_float2(v0, v1);
                if (flags & 16)
                    *(float2*)(C2 + (size_t)row * N + col) = make_float2(v0, v1);
                if (flags & 4) {
                    uint32_t hh, ll;
                    split2(v0, v1, hh, ll);
                    Ch[(size_t)row * (N >> 1) + (col >> 1)] = hh;
                    Cl[(size_t)row * (N >> 1) + (col >> 1)] = ll;
                }
            }
        }
    }
#undef LOAD_SLAB
}

// ---------------- LayerNorm -> hi/lo pairs ----------------------------------
__global__ void __launch_bounds__(256) ln_pairs(
    const float* __restrict__ x, const float* __restrict__ s,
    const float* __restrict__ b, uint32_t* __restrict__ yh,
    uint32_t* __restrict__ yl, int W)
{
    __shared__ float red[9];
    const int row = blockIdx.x;
    const int tid = threadIdx.x;
    const float* xr = x + (size_t)row * W;

    float sum = 0.f;
    for (int i = tid; i < W; i += 256) sum += xr[i];
#pragma unroll
    for (int o = 16; o > 0; o >>= 1) sum += __shfl_xor_sync(~0u, sum, o);
    if ((tid & 31) == 0) red[tid >> 5] = sum;
    __syncthreads();
    if (tid == 0) {
        float t = 0.f;
        for (int w = 0; w < 8; w++) t += red[w];
        red[8] = t;
    }
    __syncthreads();
    const float mu = red[8] / (float)W;

    float var = 0.f;
    for (int i = tid; i < W; i += 256) { float d = xr[i] - mu; var += d * d; }
    __syncthreads();
#pragma unroll
    for (int o = 16; o > 0; o >>= 1) var += __shfl_xor_sync(~0u, var, o);
    if ((tid & 31) == 0) red[tid >> 5] = var;
    __syncthreads();
    if (tid == 0) {
        float t = 0.f;
        for (int w = 0; w < 8; w++) t += red[w];
        red[8] = t;
    }
    __syncthreads();
    const float inv = rsqrtf(red[8] / (float)W + 1e-6f);

    const int Ww = W >> 1;
    for (int i = tid; i < Ww; i += 256) {
        float v0 = (xr[2*i]   - mu) * inv * s[2*i]   + b[2*i];
        float v1 = (xr[2*i+1] - mu) * inv * s[2*i+1] + b[2*i+1];
        uint32_t hh, ll;
        split2(v0, v1, hh, ll);
        yh[(size_t)row * Ww + i] = hh;
        yl[(size_t)row * Ww + i] = ll;
    }
}

// ---------------- RoPE table init -------------------------------------------
__global__ void init_rope(float* __restrict__ cosT, float* __restrict__ sinT)
{
    int idx = blockIdx.x * blockDim.x + threadIdx.x;
    if (idx >= SEQ * HD) return;
    int t = idx >> 6, d = idx & 63;
    int bh = t >> 6, r = t & 63, bw = r >> 2, ih = (r >> 1) & 1, iw = r & 1;
    float hp = (float)(bh * 2 + ih);
    float wp = (float)(bw * 2 + iw);
    int base = d & 31;
    float pos, inv;
    if (base < 16) { pos = hp; inv = powf(10000.f, -(float)base / 16.f); }
    else           { pos = wp; inv = powf(10000.f, -(float)(base - 16) / 16.f); }
    float ang = pos * inv;
    cosT[idx] = cosf(ang);
    sinT[idx] = sinf(ang);
}

// ---------------- split-KV flash attention (f16x2 exp, f16 P/V) --------------
__global__ void __launch_bounds__(256) attn_mma(
    const uint32_t* __restrict__ qh, const uint32_t* __restrict__ ql,
    const uint32_t* __restrict__ kh, const uint32_t* __restrict__ kl,
    const uint32_t* __restrict__ vth, const uint32_t* __restrict__ vtl,
    float* __restrict__ oacc, float* __restrict__ mL)
{
    __shared__ uint32_t sKh[64*33], sKl[64*33], sVh[64*33], sVl[64*33];
    const int h = blockIdx.y, qt = blockIdx.x, z = blockIdx.z;
    const int tid = threadIdx.x, w = tid >> 5, lane = tid & 31;
    const int gq = lane >> 2, l4 = lane & 3;
    const int qrow = qt * 128 + w * 16 + gq;
    const float L2E = 1.44269504088896f;

    uint32_t qfh[4][4], qfl[4][4];
    {
        const uint32_t* bh = qh + ((size_t)(h << 10) + qrow) * 32;
        const uint32_t* bl = ql + ((size_t)(h << 10) + qrow) * 32;
#pragma unroll
        for (int ks = 0; ks < 4; ks++) {
            int kp = ks * 8 + l4;
            qfh[ks][0] = bh[kp];        qfh[ks][1] = bh[8*32 + kp];
            qfh[ks][2] = bh[kp + 4];    qfh[ks][3] = bh[8*32 + kp + 4];
            qfl[ks][0] = bl[kp];        qfl[ks][1] = bl[8*32 + kp];
            qfl[ks][2] = bl[kp + 4];    qfl[ks][3] = bl[8*32 + kp + 4];
        }
    }

    float m0 = -1e30f, m1 = -1e30f, L0 = 0.f, L1 = 0.f;
    float O[8][4];
#pragma unroll
    for (int j = 0; j < 8; j++)
#pragma unroll
        for (int c = 0; c < 4; c++) O[j][c] = 0.f;

    const int kt0 = z * (SEQ / KVSPL);
    for (int kt = kt0; kt < kt0 + SEQ / KVSPL; kt += 64) {
        __syncthreads();
        {
            const uint32_t* Kh = kh + ((size_t)(h << 10) + kt) * 32;
            const uint32_t* Kl = kl + ((size_t)(h << 10) + kt) * 32;
            const uint32_t* Vh = vth + (size_t)(h * 64) * 512 + (kt >> 1);
            const uint32_t* Vl = vtl + (size_t)(h * 64) * 512 + (kt >> 1);
            for (int u = tid; u < 64 * 32; u += 256) {
                int r = u >> 5, c = u & 31;
                sKh[r * 33 + c] = Kh[r * 32 + c];
                sKl[r * 33 + c] = Kl[r * 32 + c];
                sVh[r * 33 + c] = Vh[(size_t)r * 512 + c];
                sVl[r * 33 + c] = Vl[(size_t)r * 512 + c];
            }
        }
        __syncthreads();

        float sacc[8][4];
#pragma unroll
        for (int j = 0; j < 8; j++) {
            sacc[j][0] = sacc[j][1] = sacc[j][2] = sacc[j][3] = 0.f;
            int n = j * 8 + gq;
#pragma unroll
            for (int ks = 0; ks < 4; ks++) {
                int kp = ks * 8 + l4;
                uint32_t bh0 = sKh[n * 33 + kp], bh1 = sKh[n * 33 + kp + 4];
                uint32_t bl0 = sKl[n * 33 + kp], bl1 = sKl[n * 33 + kp + 4];
                MMA_BF16(sacc[j], qfh[ks], bh0, bh1);
                MMA_BF16(sacc[j], qfh[ks], bl0, bl1);
                MMA_BF16(sacc[j], qfl[ks], bh0, bh1);
            }
        }

        float mt0 = -1e30f, mt1 = -1e30f;
#pragma unroll
        for (int j = 0; j < 8; j++) {
            mt0 = fmaxf(mt0, fmaxf(sacc[j][0], sacc[j][1]));
            mt1 = fmaxf(mt1, fmaxf(sacc[j][2], sacc[j][3]));
        }
        mt0 = fmaxf(mt0, __shfl_xor_sync(~0u, mt0, 1));
        mt0 = fmaxf(mt0, __shfl_xor_sync(~0u, mt0, 2));
        mt1 = fmaxf(mt1, __shfl_xor_sync(~0u, mt1, 1));
        mt1 = fmaxf(mt1, __shfl_xor_sync(~0u, mt1, 2));
        float mn0 = fmaxf(m0, mt0), mn1 = fmaxf(m1, mt1);
        float sc0 = __expf(m0 - mn0), sc1 = __expf(m1 - mn1);

        // P = exp(s - m) via f16x2 ex2; packed halves are the f16 A-fragments
        float ls0 = 0.f, ls1 = 0.f;
        uint32_t pf[4][4];
#pragma unroll
        for (int ks2 = 0; ks2 < 4; ks2++) {
            int j0 = 2 * ks2, j1 = j0 + 1;
            pf[ks2][0] = pexp2((sacc[j0][0] - mn0) * L2E,
                               (sacc[j0][1] - mn0) * L2E, ls0);
            pf[ks2][1] = pexp2((sacc[j0][2] - mn1) * L2E,
                               (sacc[j0][3] - mn1) * L2E, ls1);
            pf[ks2][2] = pexp2((sacc[j1][0] - mn0) * L2E,
                               (sacc[j1][1] - mn0) * L2E, ls0);
            pf[ks2][3] = pexp2((sacc[j1][2] - mn1) * L2E,
                               (sacc[j1][3] - mn1) * L2E, ls1);
        }
        ls0 += __shfl_xor_sync(~0u, ls0, 1);
        ls0 += __shfl_xor_sync(~0u, ls0, 2);
        ls1 += __shfl_xor_sync(~0u, ls1, 1);
        ls1 += __shfl_xor_sync(~0u, ls1, 2);
        L0 = L0 * sc0 + ls0;
        L1 = L1 * sc1 + ls1;
        m0 = mn0; m1 = mn1;
#pragma unroll
        for (int j = 0; j < 8; j++) {
            O[j][0] *= sc0; O[j][1] *= sc0;
            O[j][2] *= sc1; O[j][3] *= sc1;
        }

        // O += P V  (P f16 single, V f16 hi+lo: 2 passes)
#pragma unroll
        for (int jd = 0; jd < 8; jd++) {
            int n = jd * 8 + gq;
#pragma unroll
            for (int ks2 = 0; ks2 < 4; ks2++) {
                int kp = ks2 * 8 + l4;
                uint32_t bh0 = sVh[n * 33 + kp], bh1 = sVh[n * 33 + kp + 4];
                uint32_t bl0 = sVl[n * 33 + kp], bl1 = sVl[n * 33 + kp + 4];
                MMA_F16(O[jd], pf[ks2], bh0, bh1);
                MMA_F16(O[jd], pf[ks2], bl0, bl1);
            }
        }
    }

    float* ob0 = oacc + (((size_t)(z * NHEAD + h) * SEQ + qrow) * 64);
    float* ob1 = oacc + (((size_t)(z * NHEAD + h) * SEQ + qrow + 8) * 64);
#pragma unroll
    for (int jd = 0; jd < 8; jd++) {
        int d = jd * 8 + l4 * 2;
        *(float2*)(ob0 + d) = make_float2(O[jd][0], O[jd][1]);
        *(float2*)(ob1 + d) = make_float2(O[jd][2], O[jd][3]);
    }
    if (l4 == 0) {
        size_t mb = ((size_t)(z * NHEAD + h) * SEQ + qrow) * 2;
        mL[mb] = m0;  mL[mb + 1] = L0;
        mb = ((size_t)(z * NHEAD + h) * SEQ + qrow + 8) * 2;
        mL[mb] = m1;  mL[mb + 1] = L1;
    }
}

// ---------------- combine split-KV partials -> hi/lo pairs -------------------
__global__ void attn_combine(const float* __restrict__ oacc,
                             const float* __restrict__ mL,
                             uint32_t* __restrict__ oh, uint32_t* __restrict__ ol)
{
    int idx = blockIdx.x * blockDim.x + threadIdx.x;
    if (idx >= SEQ * NHEAD * 32) return;
    int dp = idx & 31, h = (idx >> 5) & 15, t = idx >> 9;

    float m[KVSPL], L[KVSPL];
    float mstar = -1e30f;
#pragma unroll
    for (int z = 0; z < KVSPL; z++) {
        size_t mb = ((size_t)(z * NHEAD + h) * SEQ + t) * 2;
        m[z] = mL[mb];  L[z] = mL[mb + 1];
        mstar = fmaxf(mstar, m[z]);
    }
    float Lsum = 0.f, o0 = 0.f, o1 = 0.f;
#pragma unroll
    for (int z = 0; z < KVSPL; z++) {
        float wz = __expf(m[z] - mstar);
        Lsum += L[z] * wz;
        const float* ob = oacc + (((size_t)(z * NHEAD + h) * SEQ + t) * 64 + dp * 2);
        o0 += ob[0] * wz;
        o1 += ob[1] * wz;
    }
    float inv = 1.0f / Lsum;
    uint32_t hh, ll;
    split2(o0 * inv, o1 * inv, hh, ll);
    oh[(size_t)t * 512 + h * 32 + dp] = hh;
    ol[(size_t)t * 512 + h * 32 + dp] = ll;
}

// ---------------- launch -----------------------------------------------------
extern "C" void kernel_launch(void* const* d_in, const int* in_sizes, int n_in,
                              void* d_out, int out_size)
{
    (void)in_sizes; (void)n_in; (void)out_size;
    const float* pixel     = (const float*)d_in[0];
    const float* conv_w    = (const float*)d_in[1];
    const float* conv_b    = (const float*)d_in[2];
    const float* pos_table = (const float*)d_in[3];
    const float* ln1_s     = (const float*)d_in[4];
    const float* ln1_b     = (const float*)d_in[5];
    const float* ln2_s     = (const float*)d_in[6];
    const float* ln2_b     = (const float*)d_in[7];
    const float* qkv_w     = (const float*)d_in[8];
    const float* qkv_b     = (const float*)d_in[9];
    const float* proj_w    = (const float*)d_in[10];
    const float* proj_b    = (const float*)d_in[11];
    const float* fc1_w     = (const float*)d_in[12];
    const float* fc1_b     = (const float*)d_in[13];
    const float* fc2_w     = (const float*)d_in[14];
    const float* fc2_b     = (const float*)d_in[15];
    const float* mrg_ln_s  = (const float*)d_in[16];
    const float* mrg_ln_b  = (const float*)d_in[17];
    const float* mrg_fc1_w = (const float*)d_in[18];
    const float* mrg_fc1_b = (const float*)d_in[19];
    const float* mrg_fc2_w = (const float*)d_in[20];
    const float* mrg_fc2_b = (const float*)d_in[21];
    const float* ds_ln_s   = (const float*)d_in[22];
    const float* ds_ln_b   = (const float*)d_in[23];
    const float* ds_fc1_w  = (const float*)d_in[24];
    const float* ds_fc1_b  = (const float*)d_in[25];
    const float* ds_fc2_w  = (const float*)d_in[26];
    const float* ds_fc2_b  = (const float*)d_in[27];
    float* out = (float*)d_out;

    uint32_t *wh, *wl, *hh, *hl, *ah, *al, *fh, *fl, *ph, *pl;
    uint32_t *qhp, *qlp, *khp, *klp, *vth, *vtl;
    uint32_t *mh, *ml, *mfh, *mfl;
    float *x, *ds, *cosT, *sinT, *mb1, *mb2, *oacc, *mLp;
    cudaGetSymbolAddress((void**)&wh,  g_wh);
    cudaGetSymbolAddress((void**)&wl,  g_wl);
    cudaGetSymbolAddress((void**)&hh,  g_hh);
    cudaGetSymbolAddress((void**)&hl,  g_hl);
    cudaGetSymbolAddress((void**)&ah,  g_ah);
    cudaGetSymbolAddress((void**)&al,  g_al);
    cudaGetSymbolAddress((void**)&fh,  g_fh);
    cudaGetSymbolAddress((void**)&fl,  g_fl);
    cudaGetSymbolAddress((void**)&ph,  g_ph);
    cudaGetSymbolAddress((void**)&pl,  g_pl);
    cudaGetSymbolAddress((void**)&qhp, g_qh);
    cudaGetSymbolAddress((void**)&qlp, g_ql);
    cudaGetSymbolAddress((void**)&khp, g_kh);
    cudaGetSymbolAddress((void**)&klp, g_kl);
    cudaGetSymbolAddress((void**)&vth, g_vth);
    cudaGetSymbolAddress((void**)&vtl, g_vtl);
    cudaGetSymbolAddress((void**)&mh,  g_mh);
    cudaGetSymbolAddress((void**)&ml,  g_ml);
    cudaGetSymbolAddress((void**)&mfh, g_mfh);
    cudaGetSymbolAddress((void**)&mfl, g_mfl);
    cudaGetSymbolAddress((void**)&x,    g_x);
    cudaGetSymbolAddress((void**)&ds,   g_ds);
    cudaGetSymbolAddress((void**)&cosT, g_cos);
    cudaGetSymbolAddress((void**)&sinT, g_sin);
    cudaGetSymbolAddress((void**)&mb1,  g_mb1);
    cudaGetSymbolAddress((void**)&mb2,  g_mb2);
    cudaGetSymbolAddress((void**)&oacc, g_oacc);
    cudaGetSymbolAddress((void**)&mLp,  g_mL);

    cudaFuncSetAttribute(gemm_pre,
                         cudaFuncAttributeMaxDynamicSharedMemorySize, GEMM_SMEM);

    // ---- single merged weight-conversion launch ----
    CvtTable tab;
    const float* srcs[9] = { conv_w, qkv_w, proj_w, fc1_w, fc2_w,
                             mrg_fc1_w, ds_fc1_w, mrg_fc2_w, ds_fc2_w };
    const uint32_t offs[9] = { W_CONV, W_QKV, W_PROJ, W_FC1, W_FC2,
                               W_MFC1, W_DFC1, W_MFC2, W_DFC2 };
    const uint32_t nws[9] = { W_QKV - W_CONV, W_PROJ - W_QKV, W_FC1 - W_PROJ,
                              W_FC2 - W_FC1, W_MFC1 - W_FC2, W_DFC1 - W_MFC1,
                              W_MFC2 - W_DFC1, W_DFC2 - W_MFC2, W_TOTAL - W_DFC2 };
    uint32_t blk = 0;
    for (int c = 0; c < 9; c++) {
        tab.src[c] = srcs[c];
        tab.dstoff[c] = offs[c];
        tab.blkstart[c] = blk;
        blk += nws[c] >> 9;
    }
    tab.blkstart[9] = blk;
    convert_all<<<blk, 256>>>(tab, wh, wl);
    convert_pairs<<<(SEQ * 768 / 2 + 255) / 256, 256>>>(pixel, ph, pl, SEQ * 768);
    init_rope<<<(SEQ * HD + 255) / 256, 256>>>(cosT, sinT);

    // patch embed + fused pos add
    gemm_pre<<<dim3(DIM / 64, SEQ / 64), 128, GEMM_SMEM>>>(
        ph, pl, wh + W_CONV, wl + W_CONV, conv_b, pos_table, x, nullptr, nullptr,
        nullptr, SEQ, DIM, 1536, 8 | 64, 0, 0, 0, 0);

    for (int i = 0; i < DEPTH; i++) {
        ln_pairs<<<SEQ, 256>>>(x, ln1_s + i * DIM, ln1_b + i * DIM, hh, hl, DIM);
        gemm_pre<<<dim3(3 * DIM / 64, SEQ / 64), 128, GEMM_SMEM>>>(
            hh, hl, wh + W_QKV + (size_t)i * (3 * DIM * DIM / 2),
            wl + W_QKV + (size_t)i * (3 * DIM * DIM / 2),
            qkv_b + (size_t)i * 3 * DIM, nullptr, nullptr, nullptr, nullptr,
            nullptr, SEQ, 3 * DIM, DIM, 32, 0, 0, 0, 0);
        attn_mma<<<dim3(SEQ / 128, NHEAD, KVSPL), 256>>>(qhp, qlp, khp, klp,
                                                         vth, vtl, oacc, mLp);
        attn_combine<<<(SEQ * NHEAD * 32) / 256, 256>>>(oacc, mLp, ah, al);
        gemm_pre<<<dim3(DIM / 64, SEQ / 64), 128, GEMM_SMEM>>>(
            ah, al, wh + W_PROJ + (size_t)i * (DIM * DIM / 2),
            wl + W_PROJ + (size_t)i * (DIM * DIM / 2),
            proj_b + (size_t)i * DIM, x, x, nullptr, nullptr,
            nullptr, SEQ, DIM, DIM, 1 | 8, 0, 0, 0, 0);
        ln_pairs<<<SEQ, 256>>>(x, ln2_s + i * DIM, ln2_b + i * DIM, hh, hl, DIM);
        gemm_pre<<<dim3(FFD / 64, SEQ / 64), 128, GEMM_SMEM>>>(
            hh, hl, wh + W_FC1 + (size_t)i * (FFD * DIM / 2),
            wl + W_FC1 + (size_t)i * (FFD * DIM / 2),
            fc1_b + (size_t)i * FFD, nullptr, nullptr, fh, fl,
            nullptr, SEQ, FFD, DIM, 2 | 4, 0, 0, 0, 0);

        int fc2_flags = 1 | 8;
        float* dup = nullptr;
        if (i == 5)  { fc2_flags |= 16; dup = ds; }
        if (i == 11) { fc2_flags |= 16; dup = ds + SEQ * DIM; }
        if (i == 17) { fc2_flags |= 16; dup = ds + 2 * SEQ * DIM; }
        if (i == 23) { fc2_flags |= 16; dup = out; }
        gemm_pre<<<dim3(DIM / 64, SEQ / 64), 128, GEMM_SMEM>>>(
            fh, fl, wh + W_FC2 + (size_t)i * (DIM * FFD / 2),
            wl + W_FC2 + (size_t)i * (DIM * FFD / 2),
            fc2_b + (size_t)i * DIM, x, x, nullptr, nullptr,
            dup, SEQ, DIM, FFD, fc2_flags, 0, 0, 0, 0);

        if (i == 0)
            bias_copy<<<104, 256>>>(mrg_fc1_b, ds_fc1_b, mrg_fc2_b, ds_fc2_b, mb1, mb2);
    }

    // ---- batched mergers ----
    ln_pairs<<<SEQ, 256>>>(x, mrg_ln_s, mrg_ln_b, mh, ml, DIM);
    for (int j = 0; j < 3; j++)
        ln_pairs<<<256, 256>>>(ds + (size_t)j * SEQ * DIM,
                               ds_ln_s + j * 4096, ds_ln_b + j * 4096,
                               mh + (size_t)(j + 1) * 524288,
                               ml + (size_t)(j + 1) * 524288, 4096);
    gemm_pre<<<dim3(4096 / 64, 256 / 64, 4), 128, GEMM_SMEM>>>(
        mh, ml, wh + W_MFC1, wl + W_MFC1, mb1, nullptr, nullptr, mfh, mfl,
        nullptr, 256, 4096, 4096, 2 | 4,
        524288, 8388608, 4096, 1048576);
    gemm_pre<<<dim3(OUTD / 64, 256 / 64, 4), 128, GEMM_SMEM>>>(
        mfh, mfl, wh + W_MFC2, wl + W_MFC2, mb2, nullptr, out + SEQ * DIM,
        nullptr, nullptr, nullptr, 256, OUTD, 4096, 8,
        524288, 5242880, 2560, 655360);
}

// round 17
// speedup vs baseline: 1.1326x; 1.0056x over previous
#include <cuda_runtime.h>
#include <cuda_bf16.h>
#include <cuda_fp16.h>
#include <math.h>
#include <stdint.h>

#define SEQ   1024
#define DIM   1024
#define NHEAD 16
#define HD    64
#define FFD   4096
#define DEPTH 24
#define OUTD  2560
#define KVSPL 4

// ---------------- weight hi/lo pools (uint32 = bf16x2 pair along K) --------
#define W_CONV   0u
#define W_QKV    786432u
#define W_PROJ   38535168u
#define W_FC1    51118080u
#define W_FC2    101449728u
#define W_MFC1   151781376u
#define W_DFC1   160169984u
#define W_MFC2   185335808u
#define W_DFC2   190578688u
#define W_TOTAL  206307328u

__device__ __align__(16) uint32_t g_wh[W_TOTAL];
__device__ __align__(16) uint32_t g_wl[W_TOTAL];

// ---------------- activation scratch ----------------------------------------
__device__ float g_x   [SEQ*DIM];
__device__ float g_cos [SEQ*HD];
__device__ float g_sin [SEQ*HD];
__device__ __align__(16) uint32_t g_hh [SEQ*DIM/2];
__device__ __align__(16) uint32_t g_hl [SEQ*DIM/2];
__device__ __align__(16) uint32_t g_ah [SEQ*DIM/2];
__device__ __align__(16) uint32_t g_al [SEQ*DIM/2];
__device__ __align__(16) uint32_t g_fh [SEQ*FFD/2];
__device__ __align__(16) uint32_t g_fl [SEQ*FFD/2];
__device__ __align__(16) uint32_t g_ph [SEQ*1536/2];
__device__ __align__(16) uint32_t g_pl [SEQ*1536/2];
__device__ __align__(16) uint32_t g_qh [NHEAD*SEQ*32];
__device__ __align__(16) uint32_t g_ql [NHEAD*SEQ*32];
__device__ __align__(16) uint32_t g_kh [NHEAD*SEQ*32];
__device__ __align__(16) uint32_t g_kl [NHEAD*SEQ*32];
__device__ __align__(16) uint32_t g_vth[NHEAD*HD*512];   // V^T f16 hi pairs
__device__ __align__(16) uint32_t g_vtl[NHEAD*HD*512];   // V^T f16 lo pairs
__device__ float g_ds  [3*SEQ*DIM];
__device__ __align__(16) uint32_t g_mh [4*524288];
__device__ __align__(16) uint32_t g_ml [4*524288];
__device__ __align__(16) uint32_t g_mfh[4*524288];
__device__ __align__(16) uint32_t g_mfl[4*524288];
__device__ float g_mb1[4*4096];
__device__ float g_mb2[4*2560];
__device__ __align__(16) float g_oacc[KVSPL*NHEAD*SEQ*HD];
__device__ float g_mL[KVSPL*NHEAD*SEQ*2];

__device__ __forceinline__ float gelu_exact(float x) {
    return 0.5f * x * (1.0f + erff(x * 0.70710678118654752f));
}

__device__ __forceinline__ void split2(float x, float y, uint32_t& hi, uint32_t& lo) {
    __nv_bfloat16 xh = __float2bfloat16(x);
    __nv_bfloat16 yh = __float2bfloat16(y);
    __nv_bfloat16 xl = __float2bfloat16(x - __bfloat162float(xh));
    __nv_bfloat16 yl = __float2bfloat16(y - __bfloat162float(yh));
    __nv_bfloat162 h2 = __halves2bfloat162(xh, yh);
    __nv_bfloat162 l2 = __halves2bfloat162(xl, yl);
    hi = *(uint32_t*)&h2;
    lo = *(uint32_t*)&l2;
}

// f16 hi/lo split (for V)
__device__ __forceinline__ void split2h(float x, float y, uint32_t& hi, uint32_t& lo) {
    __half xh = __float2half_rn(x);
    __half yh = __float2half_rn(y);
    __half xl = __float2half_rn(x - __half2float(xh));
    __half yl = __float2half_rn(y - __half2float(yh));
    __half2 h2 = __halves2half2(xh, yh);
    __half2 l2 = __halves2half2(xl, yl);
    hi = *(uint32_t*)&h2;
    lo = *(uint32_t*)&l2;
}

// packed f16x2 exp2: returns packed P, also accumulates fp32 sum
__device__ __forceinline__ uint32_t pexp2(float a0, float a1, float& sum) {
    __half2 h = __floats2half2_rn(a0, a1);
    uint32_t hu = *(uint32_t*)&h;
    uint32_t r;
    asm("ex2.approx.f16x2 %0, %1;" : "=r"(r) : "r"(hu));
    __half2 p = *(__half2*)&r;
    float2 pf = __half22float2(p);
    sum += pf.x + pf.y;
    return r;
}

#define MMA_BF16(d, a, b0, b1)                                                 \
    asm volatile("mma.sync.aligned.m16n8k16.row.col.f32.bf16.bf16.f32 "        \
                 "{%0,%1,%2,%3},{%4,%5,%6,%7},{%8,%9},{%0,%1,%2,%3};"          \
                 : "+f"(d[0]), "+f"(d[1]), "+f"(d[2]), "+f"(d[3])              \
                 : "r"(a[0]), "r"(a[1]), "r"(a[2]), "r"(a[3]), "r"(b0), "r"(b1))

#define MMA_F16(d, a, b0, b1)                                                  \
    asm volatile("mma.sync.aligned.m16n8k16.row.col.f32.f16.f16.f32 "          \
                 "{%0,%1,%2,%3},{%4,%5,%6,%7},{%8,%9},{%0,%1,%2,%3};"          \
                 : "+f"(d[0]), "+f"(d[1]), "+f"(d[2]), "+f"(d[3])              \
                 : "r"(a[0]), "r"(a[1]), "r"(a[2]), "r"(a[3]), "r"(b0), "r"(b1))

#define LDSM_X4(r, addr)                                                       \
    asm volatile("ldmatrix.sync.aligned.m8n8.x4.shared.b16 {%0,%1,%2,%3},[%4];"\
                 : "=r"((r)[0]), "=r"((r)[1]), "=r"((r)[2]), "=r"((r)[3])      \
                 : "r"(addr))

#define CP_ASYNC16(dst, src)                                                   \
    asm volatile("cp.async.cg.shared.global [%0],[%1],16;" :: "r"(dst), "l"(src))
#define CP_COMMIT  asm volatile("cp.async.commit_group;")
#define CP_WAIT1   asm volatile("cp.async.wait_group 1;")

__device__ __forceinline__ uint32_t smem_u32(const void* p) {
    return (uint32_t)__cvta_generic_to_shared(p);
}

// ---------------- merged fp32 -> bf16 hi/lo conversion -----------------------
struct CvtTable {
    const float* src[9];
    uint32_t dstoff[9];
    uint32_t blkstart[10];
};

__global__ void convert_all(CvtTable tab, uint32_t* __restrict__ dh,
                            uint32_t* __restrict__ dl)
{
    int bid = blockIdx.x;
    int c = 0;
    while (bid >= (int)tab.blkstart[c + 1]) c++;
    size_t p = (size_t)(bid - tab.blkstart[c]) * 256 + threadIdx.x;
    const float* s = tab.src[c];
    float4 v = *(const float4*)(s + 4 * p);
    uint32_t h0, l0, h1, l1;
    split2(v.x, v.y, h0, l0);
    split2(v.z, v.w, h1, l1);
    size_t o = tab.dstoff[c] + 2 * p;
    *(uint2*)(dh + o) = make_uint2(h0, h1);
    *(uint2*)(dl + o) = make_uint2(l0, l1);
}

__global__ void convert_pairs(const float* __restrict__ src,
                              uint32_t* __restrict__ dh,
                              uint32_t* __restrict__ dl, int nwords)
{
    int i = blockIdx.x * blockDim.x + threadIdx.x;
    if (2 * i >= nwords) return;
    float4 v = *(const float4*)(src + 4 * (size_t)i);
    uint32_t h0, l0, h1, l1;
    split2(v.x, v.y, h0, l0);
    split2(v.z, v.w, h1, l1);
    *(uint2*)(dh + 2 * (size_t)i) = make_uint2(h0, h1);
    *(uint2*)(dl + 2 * (size_t)i) = make_uint2(l0, l1);
}

__global__ void bias_copy(const float* __restrict__ m1, const float* __restrict__ d1,
                          const float* __restrict__ m2, const float* __restrict__ d2,
                          float* __restrict__ o1, float* __restrict__ o2)
{
    int i = blockIdx.x * blockDim.x + threadIdx.x;
    if (i < 4 * 4096) {
        int b = i >> 12, k = i & 4095;
        o1[i] = (b == 0) ? m1[k] : d1[(b - 1) * 4096 + k];
    } else if (i < 4 * 4096 + 4 * 2560) {
        int j = i - 4 * 4096;
        int b = j / 2560, k = j % 2560;
        o2[j] = (b == 0) ? m2[k] : d2[(b - 1) * 2560 + k];
    }
}

// ---------------- GEMM: 64x64 tile, 128 threads, 3-stage (proven) -----------
#define SW 20
#define T_WORDS (64 * SW)
#define STG_WORDS (4 * T_WORDS)
#define NSTAGE 3
#define GEMM_SMEM (NSTAGE * STG_WORDS * 4)

__global__ void __launch_bounds__(128, 3) gemm_pre(
    const uint32_t* __restrict__ Ah, const uint32_t* __restrict__ Al,
    const uint32_t* __restrict__ Bh, const uint32_t* __restrict__ Bl,
    const float* __restrict__ bias, const float* __restrict__ Cres,
    float* __restrict__ C, uint32_t* __restrict__ Ch, uint32_t* __restrict__ Cl,
    float* __restrict__ C2, int M, int N, int K, int flags,
    int bsAw, int bsBw, int bsBias, int bsCE)
{
    extern __shared__ uint32_t sm[];
    const int bz = blockIdx.z;
    Ah += (size_t)bz * bsAw;  Al += (size_t)bz * bsAw;
    Bh += (size_t)bz * bsBw;  Bl += (size_t)bz * bsBw;
    bias += (size_t)bz * bsBias;
    C  += (size_t)bz * bsCE;
    C2 += (size_t)bz * bsCE;
    Ch += (size_t)bz * (bsCE >> 1);
    Cl += (size_t)bz * (bsCE >> 1);

    const int bm = blockIdx.y * 64, bn = blockIdx.x * 64;
    const int tid = threadIdx.x;
    const int wid = tid >> 5, lane = tid & 31;
    const int wm = wid;
    const int Kw = K >> 1;
    const int NT = Kw >> 4;

    float acc[8][4];
#pragma unroll
    for (int j = 0; j < 8; j++)
#pragma unroll
        for (int c = 0; c < 4; c++) acc[j][c] = 0.f;

    const uint32_t smbase = smem_u32(sm);

    const int aRow  = lane & 15;
    const int aColw = (lane >> 4) << 2;
    const int bRow  = (lane & 7) + ((lane & 16) ? 8 : 0);
    const int bColw = (lane & 8) ? 4 : 0;

#define LOAD_SLAB(stagebase_, kwo_) do {                                       \
    _Pragma("unroll")                                                          \
    for (int it = 0; it < 8; it++) {                                           \
        int idx = tid + it * 128;                                              \
        int arr = idx >> 8, r = (idx >> 2) & 63, c = idx & 3;                  \
        uint32_t smoff = (uint32_t)(arr * T_WORDS + r * SW + c * 4);           \
        const uint32_t* gp;                                                    \
        if (arr == 0)      gp = Ah + (size_t)(bm + r) * Kw + (kwo_) + c * 4;   \
        else if (arr == 1) gp = Al + (size_t)(bm + r) * Kw + (kwo_) + c * 4;   \
        else if (arr == 2) gp = Bh + (size_t)(bn + r) * Kw + (kwo_) + c * 4;   \
        else               gp = Bl + (size_t)(bn + r) * Kw + (kwo_) + c * 4;   \
        CP_ASYNC16((stagebase_) + smoff * 4, gp);                              \
    }                                                                          \
} while (0)

    LOAD_SLAB(smbase, 0);
    CP_COMMIT;
    if (NT > 1) LOAD_SLAB(smbase + STG_WORDS * 4, 16);
    CP_COMMIT;

    for (int kt = 0; kt < NT; kt++) {
        const int s = kt % NSTAGE;
        CP_WAIT1;
        __syncthreads();

        if (kt + 2 < NT) {
            const uint32_t stb = smbase + ((kt + 2) % NSTAGE) * STG_WORDS * 4;
            LOAD_SLAB(stb, (kt + 2) * 16);
        }
        CP_COMMIT;

        const uint32_t base   = smbase + (uint32_t)(s * STG_WORDS) * 4;
        const uint32_t baseAh = base;
        const uint32_t baseAl = base + (uint32_t)T_WORDS * 4;
        const uint32_t baseBh = base + (uint32_t)(2 * T_WORDS) * 4;
        const uint32_t baseBl = base + (uint32_t)(3 * T_WORDS) * 4;

#pragma unroll
        for (int ks = 0; ks < 2; ks++) {
            uint32_t ah[4], al[4];
            {
                uint32_t off = (uint32_t)((wm * 16 + aRow) * SW + ks * 8 + aColw) * 4;
                LDSM_X4(ah, baseAh + off);
                LDSM_X4(al, baseAl + off);
            }
            uint32_t bh[4][4], bl[4][4];
#pragma unroll
            for (int jj = 0; jj < 4; jj++) {
                uint32_t off = (uint32_t)((jj * 16 + bRow) * SW + ks * 8 + bColw) * 4;
                LDSM_X4(bh[jj], baseBh + off);
                LDSM_X4(bl[jj], baseBl + off);
            }
#pragma unroll
            for (int jj = 0; jj < 4; jj++)
#pragma unroll
                for (int jp = 0; jp < 2; jp++)
                    MMA_BF16(acc[jj*2+jp], ah, bh[jj][jp*2], bh[jj][jp*2+1]);
#pragma unroll
            for (int jj = 0; jj < 4; jj++)
#pragma unroll
                for (int jp = 0; jp < 2; jp++)
                    MMA_BF16(acc[jj*2+jp], ah, bl[jj][jp*2], bl[jj][jp*2+1]);
#pragma unroll
            for (int jj = 0; jj < 4; jj++)
#pragma unroll
                for (int jp = 0; jp < 2; jp++)
                    MMA_BF16(acc[jj*2+jp], al, bh[jj][jp*2], bh[jj][jp*2+1]);
        }
    }

    if (flags & 32) {
        // ---- fused qkv epilogue: rope q/k + v transpose (f16 split) ----
        const int r0 = bm + wm * 16 + (lane >> 2);
        const int colbase = bn;
        const int region = colbase >> 10;
        const int h = (colbase & 1023) >> 6;
#pragma unroll
        for (int half = 0; half < 2; half++) {
            const int t = r0 + half * 8;
            float vals[8][2];
#pragma unroll
            for (int j = 0; j < 8; j++) {
                int col = colbase + j * 8 + (lane & 3) * 2;
                vals[j][0] = acc[j][half * 2 + 0] + bias[col];
                vals[j][1] = acc[j][half * 2 + 1] + bias[col + 1];
            }
            if (region < 2) {
                uint32_t* Oh = region ? g_kh : g_qh;
                uint32_t* Ol = region ? g_kl : g_ql;
                const float qs = region ? 1.0f : 0.125f;
                const size_t ob = ((size_t)(h << 10) + t) * 32;
#pragma unroll
                for (int j = 0; j < 4; j++) {
                    int d = j * 8 + (lane & 3) * 2;
                    float c0 = g_cos[t*64 + d],      s0 = g_sin[t*64 + d];
                    float c1 = g_cos[t*64 + d + 1],  s1 = g_sin[t*64 + d + 1];
                    float c2 = g_cos[t*64 + d + 32], s2 = g_sin[t*64 + d + 32];
                    float c3 = g_cos[t*64 + d + 33], s3 = g_sin[t*64 + d + 33];
                    float x1a = vals[j][0],     x1b = vals[j][1];
                    float x2a = vals[j + 4][0], x2b = vals[j + 4][1];
                    uint32_t hh, ll;
                    split2((x1a*c0 - x2a*s0) * qs, (x1b*c1 - x2b*s1) * qs, hh, ll);
                    Oh[ob + (d >> 1)] = hh;  Ol[ob + (d >> 1)] = ll;
                    split2((x2a*c2 + x1a*s2) * qs, (x2b*c3 + x1b*s3) * qs, hh, ll);
                    Oh[ob + (d >> 1) + 16] = hh;  Ol[ob + (d >> 1) + 16] = ll;
                }
            } else {
                const int tp = t >> 1;
#pragma unroll
                for (int j = 0; j < 8; j++) {
                    float p0 = __shfl_down_sync(0xFFFFFFFFu, vals[j][0], 4);
                    float p1 = __shfl_down_sync(0xFFFFFFFFu, vals[j][1], 4);
                    if ((lane & 4) == 0) {
                        int d = j * 8 + (lane & 3) * 2;
                        uint32_t hh, ll;
                        split2h(vals[j][0], p0, hh, ll);
                        g_vth[(size_t)(h * 64 + d) * 512 + tp] = hh;
                        g_vtl[(size_t)(h * 64 + d) * 512 + tp] = ll;
                        split2h(vals[j][1], p1, hh, ll);
                        g_vth[(size_t)(h * 64 + d + 1) * 512 + tp] = hh;
                        g_vtl[(size_t)(h * 64 + d + 1) * 512 + tp] = ll;
                    }
                }
            }
        }
        return;
    }

    // standard epilogue
    {
        const int r0 = bm + wm * 16 + (lane >> 2);
#pragma unroll
        for (int j = 0; j < 8; j++) {
            int col = bn + j * 8 + (lane & 3) * 2;
            float b0 = bias[col], b1 = bias[col + 1];
#pragma unroll
            for (int half = 0; half < 2; half++) {
                int row = r0 + half * 8;
                float v0 = acc[j][half * 2 + 0] + b0;
                float v1 = acc[j][half * 2 + 1] + b1;
                if (flags & 2) { v0 = gelu_exact(v0); v1 = gelu_exact(v1); }
                if (flags & 1) {
                    const float* R = Cres + (size_t)row * N + col;
                    v0 += R[0]; v1 += R[1];
                }
                if (flags & 64) {
                    int bhh = row >> 6, rr = row & 63;
                    int pid = ((bhh * 2 + ((rr >> 1) & 1)) * 48)
                              + ((rr >> 2) * 2 + (rr & 1));
                    const float* P = Cres + (size_t)pid * DIM + col;
                    v0 += P[0]; v1 += P[1];
                }
                if (flags & 8)
                    *(float2*)(C + (size_t)row * N + col) = make_float2(v0, v1);
                if (flags & 16)
                    *(float2*)(C2 + (size_t)row * N + col) = make_float2(v0, v1);
                if (flags & 4) {
                    uint32_t hh, ll;
                    split2(v0, v1, hh, ll);
                    Ch[(size_t)row * (N >> 1) + (col >> 1)] = hh;
                    Cl[(size_t)row * (N >> 1) + (col >> 1)] = ll;
                }
            }
        }
    }
#undef LOAD_SLAB
}

// ---------------- LayerNorm -> hi/lo pairs ----------------------------------
__global__ void __launch_bounds__(256) ln_pairs(
    const float* __restrict__ x, const float* __restrict__ s,
    const float* __restrict__ b, uint32_t* __restrict__ yh,
    uint32_t* __restrict__ yl, int W)
{
    __shared__ float red[9];
    const int row = blockIdx.x;
    const int tid = threadIdx.x;
    const float* xr = x + (size_t)row * W;

    float sum = 0.f;
    for (int i = tid; i < W; i += 256) sum += xr[i];
#pragma unroll
    for (int o = 16; o > 0; o >>= 1) sum += __shfl_xor_sync(~0u, sum, o);
    if ((tid & 31) == 0) red[tid >> 5] = sum;
    __syncthreads();
    if (tid == 0) {
        float t = 0.f;
        for (int w = 0; w < 8; w++) t += red[w];
        red[8] = t;
    }
    __syncthreads();
    const float mu = red[8] / (float)W;

    float var = 0.f;
    for (int i = tid; i < W; i += 256) { float d = xr[i] - mu; var += d * d; }
    __syncthreads();
#pragma unroll
    for (int o = 16; o > 0; o >>= 1) var += __shfl_xor_sync(~0u, var, o);
    if ((tid & 31) == 0) red[tid >> 5] = var;
    __syncthreads();
    if (tid == 0) {
        float t = 0.f;
        for (int w = 0; w < 8; w++) t += red[w];
        red[8] = t;
    }
    __syncthreads();
    const float inv = rsqrtf(red[8] / (float)W + 1e-6f);

    const int Ww = W >> 1;
    for (int i = tid; i < Ww; i += 256) {
        float v0 = (xr[2*i]   - mu) * inv * s[2*i]   + b[2*i];
        float v1 = (xr[2*i+1] - mu) * inv * s[2*i+1] + b[2*i+1];
        uint32_t hh, ll;
        split2(v0, v1, hh, ll);
        yh[(size_t)row * Ww + i] = hh;
        yl[(size_t)row * Ww + i] = ll;
    }
}

// ---------------- RoPE table init -------------------------------------------
__global__ void init_rope(float* __restrict__ cosT, float* __restrict__ sinT)
{
    int idx = blockIdx.x * blockDim.x + threadIdx.x;
    if (idx >= SEQ * HD) return;
    int t = idx >> 6, d = idx & 63;
    int bh = t >> 6, r = t & 63, bw = r >> 2, ih = (r >> 1) & 1, iw = r & 1;
    float hp = (float)(bh * 2 + ih);
    float wp = (float)(bw * 2 + iw);
    int base = d & 31;
    float pos, inv;
    if (base < 16) { pos = hp; inv = powf(10000.f, -(float)base / 16.f); }
    else           { pos = wp; inv = powf(10000.f, -(float)(base - 16) / 16.f); }
    float ang = pos * inv;
    cosT[idx] = cosf(ang);
    sinT[idx] = sinf(ang);
}

// ---------------- split-KV flash attention (Q in smem, 2 CTA/SM) ------------
// Q pitch 36 words (144B, 16B-aligned rows for ldmatrix).
// words: sQh 4608, sQl 4608, sKh/sKl/sVh/sVl 2112 each = 17664 (70656 B)
#define QPITCH 36
#define ATTN_SMEM (17664 * 4)
__global__ void __launch_bounds__(256, 2) attn_mma(
    const uint32_t* __restrict__ qh, const uint32_t* __restrict__ ql,
    const uint32_t* __restrict__ kh, const uint32_t* __restrict__ kl,
    const uint32_t* __restrict__ vth, const uint32_t* __restrict__ vtl,
    float* __restrict__ oacc, float* __restrict__ mL)
{
    extern __shared__ uint32_t asmem[];
    uint32_t* sQh = asmem;
    uint32_t* sQl = asmem + 4608;
    uint32_t* sKh = asmem + 9216;
    uint32_t* sKl = asmem + 11328;
    uint32_t* sVh = asmem + 13440;
    uint32_t* sVl = asmem + 15552;

    const int h = blockIdx.y, qt = blockIdx.x, z = blockIdx.z;
    const int tid = threadIdx.x, w = tid >> 5, lane = tid & 31;
    const int gq = lane >> 2, l4 = lane & 3;
    const int qrow = qt * 128 + w * 16 + gq;
    const float L2E = 1.44269504088896f;

    // stage Q tile (128 rows x 32 words, pitch 36) into smem
    {
        const uint32_t* Qh = qh + ((size_t)(h << 10) + qt * 128) * 32;
        const uint32_t* Ql = ql + ((size_t)(h << 10) + qt * 128) * 32;
        for (int u = tid; u < 128 * 32; u += 256) {
            int r = u >> 5, c = u & 31;
            sQh[r * QPITCH + c] = Qh[u];
            sQl[r * QPITCH + c] = Ql[u];
        }
    }

    const int aRow  = lane & 15;
    const int aColw = (lane >> 4) << 2;
    const uint32_t smQh = smem_u32(sQh);
    const uint32_t smQl = smem_u32(sQl);

    float m0 = -1e30f, m1 = -1e30f, L0 = 0.f, L1 = 0.f;
    float O[8][4];
#pragma unroll
    for (int j = 0; j < 8; j++)
#pragma unroll
        for (int c = 0; c < 4; c++) O[j][c] = 0.f;

    const int kt0 = z * (SEQ / KVSPL);
    for (int kt = kt0; kt < kt0 + SEQ / KVSPL; kt += 64) {
        __syncthreads();
        {
            const uint32_t* Kh = kh + ((size_t)(h << 10) + kt) * 32;
            const uint32_t* Kl = kl + ((size_t)(h << 10) + kt) * 32;
            const uint32_t* Vh = vth + (size_t)(h * 64) * 512 + (kt >> 1);
            const uint32_t* Vl = vtl + (size_t)(h * 64) * 512 + (kt >> 1);
            for (int u = tid; u < 64 * 32; u += 256) {
                int r = u >> 5, c = u & 31;
                sKh[r * 33 + c] = Kh[r * 32 + c];
                sKl[r * 33 + c] = Kl[r * 32 + c];
                sVh[r * 33 + c] = Vh[(size_t)r * 512 + c];
                sVl[r * 33 + c] = Vl[(size_t)r * 512 + c];
            }
        }
        __syncthreads();

        // S = Q K^T (Q fragments re-materialized from smem via ldmatrix)
        float sacc[8][4];
#pragma unroll
        for (int j = 0; j < 8; j++) {
            sacc[j][0] = sacc[j][1] = sacc[j][2] = sacc[j][3] = 0.f;
        }
#pragma unroll
        for (int ks = 0; ks < 4; ks++) {
            uint32_t ah[4], al[4];
            uint32_t off = (uint32_t)((w * 16 + aRow) * QPITCH + ks * 8 + aColw) * 4;
            LDSM_X4(ah, smQh + off);
            LDSM_X4(al, smQl + off);
            const int kp = ks * 8 + l4;
#pragma unroll
            for (int j = 0; j < 8; j++) {
                int n = j * 8 + gq;
                uint32_t bh0 = sKh[n * 33 + kp], bh1 = sKh[n * 33 + kp + 4];
                uint32_t bl0 = sKl[n * 33 + kp], bl1 = sKl[n * 33 + kp + 4];
                MMA_BF16(sacc[j], ah, bh0, bh1);
                MMA_BF16(sacc[j], ah, bl0, bl1);
                MMA_BF16(sacc[j], al, bh0, bh1);
            }
        }

        float mt0 = -1e30f, mt1 = -1e30f;
#pragma unroll
        for (int j = 0; j < 8; j++) {
            mt0 = fmaxf(mt0, fmaxf(sacc[j][0], sacc[j][1]));
            mt1 = fmaxf(mt1, fmaxf(sacc[j][2], sacc[j][3]));
        }
        mt0 = fmaxf(mt0, __shfl_xor_sync(~0u, mt0, 1));
        mt0 = fmaxf(mt0, __shfl_xor_sync(~0u, mt0, 2));
        mt1 = fmaxf(mt1, __shfl_xor_sync(~0u, mt1, 1));
        mt1 = fmaxf(mt1, __shfl_xor_sync(~0u, mt1, 2));
        float mn0 = fmaxf(m0, mt0), mn1 = fmaxf(m1, mt1);
        float sc0 = __expf(m0 - mn0), sc1 = __expf(m1 - mn1);

        float ls0 = 0.f, ls1 = 0.f;
        uint32_t pf[4][4];
#pragma unroll
        for (int ks2 = 0; ks2 < 4; ks2++) {
            int j0 = 2 * ks2, j1 = j0 + 1;
            pf[ks2][0] = pexp2((sacc[j0][0] - mn0) * L2E,
                               (sacc[j0][1] - mn0) * L2E, ls0);
            pf[ks2][1] = pexp2((sacc[j0][2] - mn1) * L2E,
                               (sacc[j0][3] - mn1) * L2E, ls1);
            pf[ks2][2] = pexp2((sacc[j1][0] - mn0) * L2E,
                               (sacc[j1][1] - mn0) * L2E, ls0);
            pf[ks2][3] = pexp2((sacc[j1][2] - mn1) * L2E,
                               (sacc[j1][3] - mn1) * L2E, ls1);
        }
        ls0 += __shfl_xor_sync(~0u, ls0, 1);
        ls0 += __shfl_xor_sync(~0u, ls0, 2);
        ls1 += __shfl_xor_sync(~0u, ls1, 1);
        ls1 += __shfl_xor_sync(~0u, ls1, 2);
        L0 = L0 * sc0 + ls0;
        L1 = L1 * sc1 + ls1;
        m0 = mn0; m1 = mn1;
#pragma unroll
        for (int j = 0; j < 8; j++) {
            O[j][0] *= sc0; O[j][1] *= sc0;
            O[j][2] *= sc1; O[j][3] *= sc1;
        }

        // O += P V  (P f16 single, V f16 hi+lo: 2 passes)
#pragma unroll
        for (int jd = 0; jd < 8; jd++) {
            int n = jd * 8 + gq;
#pragma unroll
            for (int ks2 = 0; ks2 < 4; ks2++) {
                int kp = ks2 * 8 + l4;
                uint32_t bh0 = sVh[n * 33 + kp], bh1 = sVh[n * 33 + kp + 4];
                uint32_t bl0 = sVl[n * 33 + kp], bl1 = sVl[n * 33 + kp + 4];
                MMA_F16(O[jd], pf[ks2], bh0, bh1);
                MMA_F16(O[jd], pf[ks2], bl0, bl1);
            }
        }
    }

    float* ob0 = oacc + (((size_t)(z * NHEAD + h) * SEQ + qrow) * 64);
    float* ob1 = oacc + (((size_t)(z * NHEAD + h) * SEQ + qrow + 8) * 64);
#pragma unroll
    for (int jd = 0; jd < 8; jd++) {
        int d = jd * 8 + l4 * 2;
        *(float2*)(ob0 + d) = make_float2(O[jd][0], O[jd][1]);
        *(float2*)(ob1 + d) = make_float2(O[jd][2], O[jd][3]);
    }
    if (l4 == 0) {
        size_t mb = ((size_t)(z * NHEAD + h) * SEQ + qrow) * 2;
        mL[mb] = m0;  mL[mb + 1] = L0;
        mb = ((size_t)(z * NHEAD + h) * SEQ + qrow + 8) * 2;
        mL[mb] = m1;  mL[mb + 1] = L1;
    }
}

// ---------------- combine split-KV partials -> hi/lo pairs -------------------
__global__ void attn_combine(const float* __restrict__ oacc,
                             const float* __restrict__ mL,
                             uint32_t* __restrict__ oh, uint32_t* __restrict__ ol)
{
    int idx = blockIdx.x * blockDim.x + threadIdx.x;
    if (idx >= SEQ * NHEAD * 32) return;
    int dp = idx & 31, h = (idx >> 5) & 15, t = idx >> 9;

    float m[KVSPL], L[KVSPL];
    float mstar = -1e30f;
#pragma unroll
    for (int z = 0; z < KVSPL; z++) {
        size_t mb = ((size_t)(z * NHEAD + h) * SEQ + t) * 2;
        m[z] = mL[mb];  L[z] = mL[mb + 1];
        mstar = fmaxf(mstar, m[z]);
    }
    float Lsum = 0.f, o0 = 0.f, o1 = 0.f;
#pragma unroll
    for (int z = 0; z < KVSPL; z++) {
        float wz = __expf(m[z] - mstar);
        Lsum += L[z] * wz;
        const float* ob = oacc + (((size_t)(z * NHEAD + h) * SEQ + t) * 64 + dp * 2);
        o0 += ob[0] * wz;
        o1 += ob[1] * wz;
    }
    float inv = 1.0f / Lsum;
    uint32_t hh, ll;
    split2(o0 * inv, o1 * inv, hh, ll);
    oh[(size_t)t * 512 + h * 32 + dp] = hh;
    ol[(size_t)t * 512 + h * 32 + dp] = ll;
}

// ---------------- launch -----------------------------------------------------
extern "C" void kernel_launch(void* const* d_in, const int* in_sizes, int n_in,
                              void* d_out, int out_size)
{
    (void)in_sizes; (void)n_in; (void)out_size;
    const float* pixel     = (const float*)d_in[0];
    const float* conv_w    = (const float*)d_in[1];
    const float* conv_b    = (const float*)d_in[2];
    const float* pos_table = (const float*)d_in[3];
    const float* ln1_s     = (const float*)d_in[4];
    const float* ln1_b     = (const float*)d_in[5];
    const float* ln2_s     = (const float*)d_in[6];
    const float* ln2_b     = (const float*)d_in[7];
    const float* qkv_w     = (const float*)d_in[8];
    const float* qkv_b     = (const float*)d_in[9];
    const float* proj_w    = (const float*)d_in[10];
    const float* proj_b    = (const float*)d_in[11];
    const float* fc1_w     = (const float*)d_in[12];
    const float* fc1_b     = (const float*)d_in[13];
    const float* fc2_w     = (const float*)d_in[14];
    const float* fc2_b     = (const float*)d_in[15];
    const float* mrg_ln_s  = (const float*)d_in[16];
    const float* mrg_ln_b  = (const float*)d_in[17];
    const float* mrg_fc1_w = (const float*)d_in[18];
    const float* mrg_fc1_b = (const float*)d_in[19];
    const float* mrg_fc2_w = (const float*)d_in[20];
    const float* mrg_fc2_b = (const float*)d_in[21];
    const float* ds_ln_s   = (const float*)d_in[22];
    const float* ds_ln_b   = (const float*)d_in[23];
    const float* ds_fc1_w  = (const float*)d_in[24];
    const float* ds_fc1_b  = (const float*)d_in[25];
    const float* ds_fc2_w  = (const float*)d_in[26];
    const float* ds_fc2_b  = (const float*)d_in[27];
    float* out = (float*)d_out;

    uint32_t *wh, *wl, *hh, *hl, *ah, *al, *fh, *fl, *ph, *pl;
    uint32_t *qhp, *qlp, *khp, *klp, *vth, *vtl;
    uint32_t *mh, *ml, *mfh, *mfl;
    float *x, *ds, *cosT, *sinT, *mb1, *mb2, *oacc, *mLp;
    cudaGetSymbolAddress((void**)&wh,  g_wh);
    cudaGetSymbolAddress((void**)&wl,  g_wl);
    cudaGetSymbolAddress((void**)&hh,  g_hh);
    cudaGetSymbolAddress((void**)&hl,  g_hl);
    cudaGetSymbolAddress((void**)&ah,  g_ah);
    cudaGetSymbolAddress((void**)&al,  g_al);
    cudaGetSymbolAddress((void**)&fh,  g_fh);
    cudaGetSymbolAddress((void**)&fl,  g_fl);
    cudaGetSymbolAddress((void**)&ph,  g_ph);
    cudaGetSymbolAddress((void**)&pl,  g_pl);
    cudaGetSymbolAddress((void**)&qhp, g_qh);
    cudaGetSymbolAddress((void**)&qlp, g_ql);
    cudaGetSymbolAddress((void**)&khp, g_kh);
    cudaGetSymbolAddress((void**)&klp, g_kl);
    cudaGetSymbolAddress((void**)&vth, g_vth);
    cudaGetSymbolAddress((void**)&vtl, g_vtl);
    cudaGetSymbolAddress((void**)&mh,  g_mh);
    cudaGetSymbolAddress((void**)&ml,  g_ml);
    cudaGetSymbolAddress((void**)&mfh, g_mfh);
    cudaGetSymbolAddress((void**)&mfl, g_mfl);
    cudaGetSymbolAddress((void**)&x,    g_x);
    cudaGetSymbolAddress((void**)&ds,   g_ds);
    cudaGetSymbolAddress((void**)&cosT, g_cos);
    cudaGetSymbolAddress((void**)&sinT, g_sin);
    cudaGetSymbolAddress((void**)&mb1,  g_mb1);
    cudaGetSymbolAddress((void**)&mb2,  g_mb2);
    cudaGetSymbolAddress((void**)&oacc, g_oacc);
    cudaGetSymbolAddress((void**)&mLp,  g_mL);

    cudaFuncSetAttribute(gemm_pre,
                         cudaFuncAttributeMaxDynamicSharedMemorySize, GEMM_SMEM);
    cudaFuncSetAttribute(attn_mma,
                         cudaFuncAttributeMaxDynamicSharedMemorySize, ATTN_SMEM);

    // ---- single merged weight-conversion launch ----
    CvtTable tab;
    const float* srcs[9] = { conv_w, qkv_w, proj_w, fc1_w, fc2_w,
                             mrg_fc1_w, ds_fc1_w, mrg_fc2_w, ds_fc2_w };
    const uint32_t offs[9] = { W_CONV, W_QKV, W_PROJ, W_FC1, W_FC2,
                               W_MFC1, W_DFC1, W_MFC2, W_DFC2 };
    const uint32_t nws[9] = { W_QKV - W_CONV, W_PROJ - W_QKV, W_FC1 - W_PROJ,
                              W_FC2 - W_FC1, W_MFC1 - W_FC2, W_DFC1 - W_MFC1,
                              W_MFC2 - W_DFC1, W_DFC2 - W_MFC2, W_TOTAL - W_DFC2 };
    uint32_t blk = 0;
    for (int c = 0; c < 9; c++) {
        tab.src[c] = srcs[c];
        tab.dstoff[c] = offs[c];
        tab.blkstart[c] = blk;
        blk += nws[c] >> 9;
    }
    tab.blkstart[9] = blk;
    convert_all<<<blk, 256>>>(tab, wh, wl);
    convert_pairs<<<(SEQ * 768 / 2 + 255) / 256, 256>>>(pixel, ph, pl, SEQ * 768);
    init_rope<<<(SEQ * HD + 255) / 256, 256>>>(cosT, sinT);

    // patch embed + fused pos add
    gemm_pre<<<dim3(DIM / 64, SEQ / 64), 128, GEMM_SMEM>>>(
        ph, pl, wh + W_CONV, wl + W_CONV, conv_b, pos_table, x, nullptr, nullptr,
        nullptr, SEQ, DIM, 1536, 8 | 64, 0, 0, 0, 0);

    for (int i = 0; i < DEPTH; i++) {
        ln_pairs<<<SEQ, 256>>>(x, ln1_s + i * DIM, ln1_b + i * DIM, hh, hl, DIM);
        gemm_pre<<<dim3(3 * DIM / 64, SEQ / 64), 128, GEMM_SMEM>>>(
            hh, hl, wh + W_QKV + (size_t)i * (3 * DIM * DIM / 2),
            wl + W_QKV + (size_t)i * (3 * DIM * DIM / 2),
            qkv_b + (size_t)i * 3 * DIM, nullptr, nullptr, nullptr, nullptr,
            nullptr, SEQ, 3 * DIM, DIM, 32, 0, 0, 0, 0);
        attn_mma<<<dim3(SEQ / 128, NHEAD, KVSPL), 256, ATTN_SMEM>>>(
            qhp, qlp, khp, klp, vth, vtl, oacc, mLp);
        attn_combine<<<(SEQ * NHEAD * 32) / 256, 256>>>(oacc, mLp, ah, al);
        gemm_pre<<<dim3(DIM / 64, SEQ / 64), 128, GEMM_SMEM>>>(
            ah, al, wh + W_PROJ + (size_t)i * (DIM * DIM / 2),
            wl + W_PROJ + (size_t)i * (DIM * DIM / 2),
            proj_b + (size_t)i * DIM, x, x, nullptr, nullptr,
            nullptr, SEQ, DIM, DIM, 1 | 8, 0, 0, 0, 0);
        ln_pairs<<<SEQ, 256>>>(x, ln2_s + i * DIM, ln2_b + i * DIM, hh, hl, DIM);
        gemm_pre<<<dim3(FFD / 64, SEQ / 64), 128, GEMM_SMEM>>>(
            hh, hl, wh + W_FC1 + (size_t)i * (FFD * DIM / 2),
            wl + W_FC1 + (size_t)i * (FFD * DIM / 2),
            fc1_b + (size_t)i * FFD, nullptr, nullptr, fh, fl,
            nullptr, SEQ, FFD, DIM, 2 | 4, 0, 0, 0, 0);

        int fc2_flags = 1 | 8;
        float* dup = nullptr;
        if (i == 5)  { fc2_flags |= 16; dup = ds; }
        if (i == 11) { fc2_flags |= 16; dup = ds + SEQ * DIM; }
        if (i == 17) { fc2_flags |= 16; dup = ds + 2 * SEQ * DIM; }
        if (i == 23) { fc2_flags |= 16; dup = out; }
        gemm_pre<<<dim3(DIM / 64, SEQ / 64), 128, GEMM_SMEM>>>(
            fh, fl, wh + W_FC2 + (size_t)i * (DIM * FFD / 2),
            wl + W_FC2 + (size_t)i * (DIM * FFD / 2),
            fc2_b + (size_t)i * DIM, x, x, nullptr, nullptr,
            dup, SEQ, DIM, FFD, fc2_flags, 0, 0, 0, 0);

        if (i == 0)
            bias_copy<<<104, 256>>>(mrg_fc1_b, ds_fc1_b, mrg_fc2_b, ds_fc2_b, mb1, mb2);
    }

    // ---- batched mergers ----
    ln_pairs<<<SEQ, 256>>>(x, mrg_ln_s, mrg_ln_b, mh, ml, DIM);
    for (int j = 0; j < 3; j++)
        ln_pairs<<<256, 256>>>(ds + (size_t)j * SEQ * DIM,
                               ds_ln_s + j * 4096, ds_ln_b + j * 4096,
                               mh + (size_t)(j + 1) * 524288,
                               ml + (size_t)(j + 1) * 524288, 4096);
    gemm_pre<<<dim3(4096 / 64, 256 / 64, 4), 128, GEMM_SMEM>>>(
        mh, ml, wh + W_MFC1, wl + W_MFC1, mb1, nullptr, nullptr, mfh, mfl,
        nullptr, 256, 4096, 4096, 2 | 4,
        524288, 8388608, 4096, 1048576);
    gemm_pre<<<dim3(OUTD / 64, 256 / 64, 4), 128, GEMM_SMEM>>>(
        mfh, mfl, wh + W_MFC2, wl + W_MFC2, mb2, nullptr, out + SEQ * DIM,
        nullptr, nullptr, nullptr, 256, OUTD, 4096, 8,
        524288, 5242880, 2560, 655360);
}